// round 12
// baseline (speedup 1.0000x reference)
#include <cuda_runtime.h>
#include <math.h>

#define NN 8192
#define EE 262144
#define KK1 4096
#define KK2 2048
#define KK3 1024
#define NG 64

typedef unsigned int u32;
typedef unsigned long long u64;

constexpr int NWB2 = KK1 / 32;
constexpr int NWB4 = KK2 / 32;
constexpr int NWB6 = KK3 / 32;
constexpr int NSW2 = NWB2 / 32;
constexpr int NSW4 = NWB4 / 32;
constexpr int NSW6 = NWB6 / 32;

// ------------------------- workspace layout (float units) --------------------
constexpr size_t O_X1   = 0;                 constexpr size_t S_X1   = (size_t)NN*32;
constexpr size_t O_X2   = O_X1+S_X1;         constexpr size_t S_X2   = (size_t)KK1*32;
constexpr size_t O_X3   = O_X2+S_X2;         constexpr size_t S_X3   = (size_t)KK1*64;
constexpr size_t O_X4   = O_X3+S_X3;         constexpr size_t S_X4   = (size_t)KK2*64;
constexpr size_t O_X5   = O_X4+S_X4;         constexpr size_t S_X5   = (size_t)KK2*128;
constexpr size_t O_X6   = O_X5+S_X5;         constexpr size_t S_X6   = (size_t)KK3*128;
constexpr size_t O_X7   = O_X6+S_X6;         constexpr size_t S_X7   = (size_t)KK3*256;
constexpr size_t O_X9   = O_X7+S_X7;         constexpr size_t S_X9   = (size_t)KK2*128;
constexpr size_t O_X11  = O_X9+S_X9;         constexpr size_t S_X11  = (size_t)KK1*64;
constexpr size_t O_ZA   = O_X11+S_X11;       constexpr size_t S_ZA   = 262144;
constexpr size_t O_ZB   = O_ZA+S_ZA;         constexpr size_t S_ZB   = 262144;
constexpr size_t O_COL  = O_ZB+S_ZB;         constexpr size_t S_COL  = EE;
constexpr size_t O_DEG0 = O_COL+S_COL;       constexpr size_t S_DEG0 = NN;
constexpr size_t O_DINV0= O_DEG0+S_DEG0;     constexpr size_t S_DINV0= NN;
constexpr size_t O_DINV2= O_DINV0+S_DINV0;   constexpr size_t S_DINV2= KK1;
constexpr size_t O_DINV4= O_DINV2+S_DINV2;   constexpr size_t S_DINV4= KK2;
constexpr size_t O_DINV6= O_DINV4+S_DINV4;   constexpr size_t S_DINV6= KK3;
constexpr size_t O_S    = O_DINV6+S_DINV6;   constexpr size_t S_S    = NN;
constexpr size_t O_KEY  = O_S+S_S;           constexpr size_t S_KEY  = (size_t)NN*2;
constexpr size_t O_RANK = O_KEY+S_KEY;       constexpr size_t S_RANK = NN;
constexpr size_t O_POS0 = O_RANK+S_RANK;     constexpr size_t S_POS0 = NN;
constexpr size_t O_POS4 = O_POS0+S_POS0;     constexpr size_t S_POS4 = KK1;
constexpr size_t O_POS6 = O_POS4+S_POS4;     constexpr size_t S_POS6 = KK2;
constexpr size_t O_RP   = O_POS6+S_POS6;     constexpr size_t S_RP   = NN+8;
constexpr size_t O_OFF  = O_RP+S_RP;         constexpr size_t S_OFF  = NN;
constexpr size_t O_BM2  = O_OFF+S_OFF;       constexpr size_t S_BM2  = (size_t)KK1*NWB2;
constexpr size_t O_BM4  = O_BM2+S_BM2;       constexpr size_t S_BM4  = (size_t)KK2*NWB4;
constexpr size_t O_BM6  = O_BM4+S_BM4;       constexpr size_t S_BM6  = (size_t)KK3*NWB6;
constexpr size_t O_SUM2 = O_BM6+S_BM6;       constexpr size_t S_SUM2 = (size_t)KK1*NSW2;
constexpr size_t O_SUM4 = O_SUM2+S_SUM2;     constexpr size_t S_SUM4 = (size_t)KK2*NSW4;
constexpr size_t O_SUM6 = O_SUM4+S_SUM4;     constexpr size_t S_SUM6 = (size_t)KK3*NSW6;
constexpr size_t O_GSUM = O_SUM6+S_SUM6;     constexpr size_t S_GSUM = (size_t)NG*32;
constexpr size_t O_GMAX = O_GSUM+S_GSUM;     constexpr size_t S_GMAX = (size_t)NG*32;
constexpr size_t O_CNT  = O_GMAX+S_GMAX;     constexpr size_t S_CNT  = NG;
constexpr size_t WS_TOTAL = O_CNT + S_CNT;

__device__ __align__(256) float g_ws[WS_TOTAL];
__device__ unsigned g_arrive = 0;

// ------------------------------- helpers -------------------------------------
__device__ __forceinline__ float eluf(float x) { return x > 0.f ? x : expm1f(x); }
__device__ __forceinline__ unsigned ford(float f) {
    unsigned u = __float_as_uint(f);
    return (u & 0x80000000u) ? ~u : (u | 0x80000000u);
}
__device__ __forceinline__ float unford(unsigned u) {
    return __uint_as_float((u & 0x80000000u) ? (u & 0x7fffffffu) : ~u);
}

// chip-wide barrier: release-arrive / acquire-spin (all blocks resident)
__device__ __forceinline__ void gsync() {
    __syncthreads();
    if (threadIdx.x == 0) {
        unsigned t;
        asm volatile("atom.release.gpu.add.u32 %0, [%1], 1;"
                     : "=r"(t) : "l"(&g_arrive) : "memory");
        unsigned target = (t / gridDim.x + 1u) * gridDim.x;
        unsigned v;
        do {
            asm volatile("ld.acquire.gpu.u32 %0, [%1];"
                         : "=r"(v) : "l"(&g_arrive) : "memory");
        } while (v < target);
    }
    __syncthreads();
}

__device__ __forceinline__ void zerof(float* p, int n) {
    int gt = blockIdx.x * blockDim.x + threadIdx.x, NT = gridDim.x * blockDim.x;
    for (int i = gt; i < n; i += NT) p[i] = 0.f;
}

// ---------------------------- phase device funcs ------------------------------

__device__ __forceinline__ float a_elem(const float* __restrict__ X,
                                        const int* __restrict__ pos,
                                        const float* __restrict__ skip,
                                        int F1, int F2, int K, int gi, int kk) {
    if (!pos) return X[(size_t)gi * K + kk];
    if (kk < F1) {
        int p = pos[gi];
        return (p >= 0) ? eluf(X[(size_t)p * F1 + kk]) : 0.f;
    }
    return eluf(skip[(size_t)gi * F2 + (kk - F1)]);
}

// 64x64-tile GEMM, 512 threads, 2x4 micro; split-K atomicAdd accumulate.
__device__ void gemm64_dev(const float* __restrict__ X, const int* __restrict__ pos,
                           const float* __restrict__ skip, int F1, int F2,
                           const float* __restrict__ W, float* __restrict__ out,
                           int n, int K, int M, float* sh, int bstart, int bstride,
                           int SK) {
    float* As = sh;               // [16][66] k-major (m index)
    float* Bs = sh + 16 * 66;     // [16][68]  (68 keeps float4 rows 16B aligned)
    int tid = threadIdx.x;
    int tm = (tid >> 4) << 1;     // 0..62, 2 rows
    int tn = (tid & 15) << 2;     // 0..60, 4 cols
    int lm = tid >> 4, lk = tid & 15;   // A loader: rows lm, lm+32
    int bk = tid >> 6, bj = tid & 63;   // B loader: rows bk, bk+8
    int ntn = (M + 63) >> 6;
    int ntm = n >> 6;
    int ntile = ntm * ntn;
    int njobs = ntile * SK;
    int Kb = K / SK;
    for (int j = bstart; j < njobs; j += bstride) {
        int t = j % ntile, kh = j / ntile;
        int kbeg = kh * Kb, kend = kbeg + Kb;
        int bm = (t / ntn) << 6, bn = (t % ntn) << 6;
        float acc[2][4];
#pragma unroll
        for (int r = 0; r < 2; r++)
#pragma unroll
            for (int c = 0; c < 4; c++) acc[r][c] = 0.f;
        float ra0 = a_elem(X, pos, skip, F1, F2, K, bm + lm, kbeg + lk);
        float ra1 = a_elem(X, pos, skip, F1, F2, K, bm + lm + 32, kbeg + lk);
        float rb0 = (bn + bj < M) ? W[(size_t)(kbeg + bk) * M + (bn + bj)] : 0.f;
        float rb1 = (bn + bj < M) ? W[(size_t)(kbeg + bk + 8) * M + (bn + bj)] : 0.f;
        for (int kk = kbeg; kk < kend; kk += 16) {
            __syncthreads();
            As[lk * 66 + lm] = ra0;
            As[lk * 66 + lm + 32] = ra1;
            Bs[bk * 68 + bj] = rb0;
            Bs[(bk + 8) * 68 + bj] = rb1;
            __syncthreads();
            if (kk + 16 < kend) {
                ra0 = a_elem(X, pos, skip, F1, F2, K, bm + lm, kk + 16 + lk);
                ra1 = a_elem(X, pos, skip, F1, F2, K, bm + lm + 32, kk + 16 + lk);
                rb0 = (bn + bj < M) ? W[(size_t)(kk + 16 + bk) * M + (bn + bj)] : 0.f;
                rb1 = (bn + bj < M) ? W[(size_t)(kk + 24 + bk) * M + (bn + bj)] : 0.f;
            }
#pragma unroll
            for (int k = 0; k < 16; k++) {
                float2 aa = *(const float2*)&As[k * 66 + tm];
                float4 bb = *(const float4*)&Bs[k * 68 + tn];
                acc[0][0] += aa.x * bb.x; acc[0][1] += aa.x * bb.y;
                acc[0][2] += aa.x * bb.z; acc[0][3] += aa.x * bb.w;
                acc[1][0] += aa.y * bb.x; acc[1][1] += aa.y * bb.y;
                acc[1][2] += aa.y * bb.z; acc[1][3] += aa.y * bb.w;
            }
        }
        int gi = bm + tm, gj = bn + tn;
#pragma unroll
        for (int r = 0; r < 2; r++)
#pragma unroll
            for (int c = 0; c < 4; c++)
                if (gj + c < M)
                    atomicAdd(&out[(size_t)(gi + r) * M + gj + c], acc[r][c]);
    }
}

// 64x32-tile GEMM for M==32, 512 threads, 2x2 micro — full utilization.
__device__ void gemm32_dev(const float* __restrict__ X, const int* __restrict__ pos,
                           const float* __restrict__ skip, int F1, int F2,
                           const float* __restrict__ W, float* __restrict__ out,
                           int n, int K, float* sh, int bstart, int bstride,
                           int SK) {
    float* As = sh;               // [16][66]
    float* Bs = sh + 16 * 66;     // [16][34] (34 keeps float2 rows 8B aligned)
    int tid = threadIdx.x;
    int tm = (tid >> 4) << 1;     // 0..62
    int tn = (tid & 15) << 1;     // 0..30
    int lm = tid >> 4, lk = tid & 15;
    int bk = tid >> 5, bj = tid & 31;   // 512 = 16x32 exactly
    int ntm = n >> 6;
    int njobs = ntm * SK;
    int Kb = K / SK;
    for (int j = bstart; j < njobs; j += bstride) {
        int t = j % ntm, kh = j / ntm;
        int kbeg = kh * Kb, kend = kbeg + Kb;
        int bm = t << 6;
        float a00 = 0.f, a01 = 0.f, a10 = 0.f, a11 = 0.f;
        float ra0 = a_elem(X, pos, skip, F1, F2, K, bm + lm, kbeg + lk);
        float ra1 = a_elem(X, pos, skip, F1, F2, K, bm + lm + 32, kbeg + lk);
        float rb  = W[(size_t)(kbeg + bk) * 32 + bj];
        for (int kk = kbeg; kk < kend; kk += 16) {
            __syncthreads();
            As[lk * 66 + lm] = ra0;
            As[lk * 66 + lm + 32] = ra1;
            Bs[bk * 34 + bj] = rb;
            __syncthreads();
            if (kk + 16 < kend) {
                ra0 = a_elem(X, pos, skip, F1, F2, K, bm + lm, kk + 16 + lk);
                ra1 = a_elem(X, pos, skip, F1, F2, K, bm + lm + 32, kk + 16 + lk);
                rb  = W[(size_t)(kk + 16 + bk) * 32 + bj];
            }
#pragma unroll
            for (int k = 0; k < 16; k++) {
                float2 aa = *(const float2*)&As[k * 66 + tm];
                float2 bb = *(const float2*)&Bs[k * 34 + tn];
                a00 += aa.x * bb.x; a01 += aa.x * bb.y;
                a10 += aa.y * bb.x; a11 += aa.y * bb.y;
            }
        }
        int gi = bm + tm, gj = tn;
        atomicAdd(&out[(size_t)gi * 32 + gj], a00);
        atomicAdd(&out[(size_t)gi * 32 + gj + 1], a01);
        atomicAdd(&out[(size_t)(gi + 1) * 32 + gj], a10);
        atomicAdd(&out[(size_t)(gi + 1) * 32 + gj + 1], a11);
    }
}

// rank: 1024-row i-tiles, 2 rows per thread (512 thr); CH-wide j-chunks in smem
__device__ void rank_dev(const u64* __restrict__ key, int n, int CH,
                         int* __restrict__ rank, u64* shk) {
    int nti = n >> 10;
    int ntj = n / CH;
    for (int t = blockIdx.x; t < nti * ntj; t += gridDim.x) {
        int ti = t / ntj, tj = t - ti * ntj;
        int i0 = (ti << 10) + threadIdx.x;
        int j0 = tj * CH;
        __syncthreads();
        for (int l = threadIdx.x; l < CH; l += 512) shk[l] = key[j0 + l];
        __syncthreads();
        u64 ka = key[i0], kb = key[i0 + 512];
        int ca = 0, cb = 0;
#pragma unroll 8
        for (int j = 0; j < CH; j++) {
            u64 kj = shk[j];
            ca += (kj > ka) ? 1 : 0;
            cb += (kj > kb) ? 1 : 0;
        }
        if (ca) atomicAdd(&rank[i0], ca);
        if (cb) atomicAdd(&rank[i0 + 512], cb);
    }
}

__device__ void gather_dev(const float* __restrict__ x, const float* __restrict__ s,
                           const int* __restrict__ rank, int n, int k, int F,
                           float* __restrict__ out, int* __restrict__ pos) {
    int gt = blockIdx.x * blockDim.x + threadIdx.x, NT = gridDim.x * blockDim.x;
    for (int t = gt; t < n * F; t += NT) {
        int i = t / F, f = t - i * F;
        int r = rank[i];
        if (f == 0) pos[i] = (r < k) ? r : -1;
        if (r < k) {
            float gate = 1.f / (1.f + expf(-s[i]));
            out[(size_t)r * F + f] = eluf(x[t] * gate);
        }
    }
}

__device__ void bmfilter_dev(const u32* __restrict__ bms, const u32* __restrict__ ssum,
                             int nws, int nssw, int nsrc, const int* __restrict__ rank,
                             int k, int nwd, u32* __restrict__ bmd) {
    int lane = threadIdx.x & 31;
    int wg = (blockIdx.x * blockDim.x + threadIdx.x) >> 5;
    int NWp = (gridDim.x * blockDim.x) >> 5;
    for (int i = wg; i < nsrc; i += NWp) {
        int b = rank[i];
        if (b >= k) continue;
        const u32* row = bms + (size_t)i * nws;
        const u32* srow = ssum + (size_t)i * nssw;
        for (int w = lane; w < nws; w += 32) {
            if (!((srow[w >> 5] >> (w & 31)) & 1u)) continue;
            u32 word = row[w];
            while (word) {
                int bit = __ffs(word) - 1; word &= word - 1;
                int ps = rank[(w << 5) + bit];
                if (ps < k) atomicOr(&bmd[(size_t)b * nwd + (ps >> 5)], 1u << (ps & 31));
            }
        }
    }
}

__device__ void dinvsum_dev(const u32* __restrict__ bm, int n, int nw, int nsw,
                            float* __restrict__ dv, u32* __restrict__ sum) {
    int lane = threadIdx.x & 31;
    int wg = (blockIdx.x * blockDim.x + threadIdx.x) >> 5;
    int NWp = (gridDim.x * blockDim.x) >> 5;
    for (int r = wg; r < n; r += NWp) {
        int c = 0;
        for (int g = 0; g < nsw; g++) {
            u32 word = bm[(size_t)r * nw + (g << 5) + lane];
            u32 m = __ballot_sync(0xffffffffu, word != 0u);
            c += __popc(word);
            if (lane == 0) sum[(size_t)r * nsw + g] = m;
        }
#pragma unroll
        for (int o = 16; o > 0; o >>= 1) c += __shfl_xor_sync(0xffffffffu, c, o);
        if (lane == 0) dv[r] = rsqrtf((float)(c + 1));
    }
}

// bitmap SpMM; NSEG column segments per row (register-pressure control).
template<int FW, int NSEG>
__device__ void spmm_dev(const u32* __restrict__ bm, const u32* __restrict__ sum,
                         int nw, int nsw, const float* __restrict__ z,
                         const float* __restrict__ dv, const float* __restrict__ bias,
                         float* __restrict__ out, int n,
                         const float* __restrict__ p, float* __restrict__ ss,
                         u64* __restrict__ key) {
    const int F = FW * 32 * NSEG;
    const int NB = (FW <= 2) ? 4 : 2;
    int lane = threadIdx.x & 31;
    int wg = (blockIdx.x * blockDim.x + threadIdx.x) >> 5;
    int NWp = (gridDim.x * blockDim.x) >> 5;
    float invn = 0.f;
    if (p && NSEG == 1) {
        float q = 0.f;
#pragma unroll
        for (int c = 0; c < FW; c++) { float v = p[lane + 32 * c]; q += v * v; }
#pragma unroll
        for (int o = 16; o > 0; o >>= 1) q += __shfl_xor_sync(0xffffffffu, q, o);
        invn = rsqrtf(q);
    }
    for (int t = wg; t < n * NSEG; t += NWp) {
        int r = (NSEG == 1) ? t : (t / NSEG);
        int co = (NSEG == 1) ? 0 : ((t - r * NSEG) * FW * 32);
        float dr = dv[r];
        float acc[FW];
#pragma unroll
        for (int c = 0; c < FW; c++)
            acc[c] = dr * z[(size_t)r * F + co + lane + 32 * c];
        const u32* row = bm + (size_t)r * nw;
        const u32* srow = sum + (size_t)r * nsw;
        int nbuf[NB];
        int m = 0;
        auto flush = [&](int mc) {
            float dvs[NB];
            float tmp[NB][FW];
#pragma unroll
            for (int i = 0; i < NB; i++) if (i < mc) dvs[i] = dv[nbuf[i]];
#pragma unroll
            for (int i = 0; i < NB; i++) if (i < mc) {
                const float* zs = z + (size_t)nbuf[i] * F + co + lane;
#pragma unroll
                for (int c = 0; c < FW; c++) tmp[i][c] = zs[32 * c];
            }
#pragma unroll
            for (int i = 0; i < NB; i++) if (i < mc)
#pragma unroll
                for (int c = 0; c < FW; c++) acc[c] += dvs[i] * tmp[i][c];
        };
        for (int sw = 0; sw < nsw; sw++) {
            u32 sword = srow[sw];
            while (sword) {
                int wb = __ffs(sword) - 1; sword &= sword - 1;
                int w = (sw << 5) + wb;
                u32 word = row[w];
                while (word) {
                    int b = __ffs(word) - 1; word &= word - 1;
                    nbuf[m++] = (w << 5) + b;
                    if (m == NB) { flush(NB); m = 0; }
                }
            }
        }
        if (m) flush(m);
        float sc = 0.f;
#pragma unroll
        for (int c = 0; c < FW; c++) {
            float v = eluf(dr * acc[c] + bias[co + lane + 32 * c]);
            out[(size_t)r * F + co + lane + 32 * c] = v;
            if (p && NSEG == 1) sc += v * p[lane + 32 * c];
        }
        if (p && NSEG == 1) {
#pragma unroll
            for (int o = 16; o > 0; o >>= 1) sc += __shfl_xor_sync(0xffffffffu, sc, o);
            if (lane == 0) {
                float sv = sc * invn;
                ss[r] = sv;
                key[r] = ((u64)ford(sv) << 32) | (u32)(~r);
            }
        }
    }
}

__device__ void csragg_dev(const float* __restrict__ z, const int* __restrict__ rp,
                           const int* __restrict__ col, const float* __restrict__ dv,
                           const float* __restrict__ bias, float* __restrict__ out,
                           const float* __restrict__ p, float* __restrict__ ss,
                           u64* __restrict__ key,
                           const int* __restrict__ batch, float* __restrict__ gsum,
                           u32* __restrict__ gmax, float* __restrict__ cnt) {
    int lane = threadIdx.x & 31;
    int wg = (blockIdx.x * blockDim.x + threadIdx.x) >> 5;
    int NWp = (gridDim.x * blockDim.x) >> 5;
    float invn = 0.f, pv = 0.f;
    if (p) {
        pv = p[lane];
        float q = pv * pv;
#pragma unroll
        for (int o = 16; o > 0; o >>= 1) q += __shfl_xor_sync(0xffffffffu, q, o);
        invn = rsqrtf(q);
    }
    float bl = bias[lane];
    for (int r = wg; r < NN; r += NWp) {
        float dr = dv[r];
        float acc = dr * z[r * 32 + lane];
        int e = rp[r], e1 = rp[r + 1];
        for (; e + 3 < e1; e += 4) {
            int s[4]; float d[4], v[4];
#pragma unroll
            for (int i = 0; i < 4; i++) s[i] = col[e + i];
#pragma unroll
            for (int i = 0; i < 4; i++) { d[i] = dv[s[i]]; v[i] = z[s[i] * 32 + lane]; }
#pragma unroll
            for (int i = 0; i < 4; i++) acc += d[i] * v[i];
        }
        for (; e < e1; e++) { int s = col[e]; acc += dv[s] * z[s * 32 + lane]; }
        float val = eluf(dr * acc + bl);
        if (out) {
            out[r * 32 + lane] = val;
            if (p) {
                float sc = val * pv;
#pragma unroll
                for (int o = 16; o > 0; o >>= 1) sc += __shfl_xor_sync(0xffffffffu, sc, o);
                if (lane == 0) {
                    float sv = sc * invn;
                    ss[r] = sv;
                    key[r] = ((u64)ford(sv) << 32) | (u32)(~r);
                }
            }
        } else {
            int g = batch[r];
            atomicAdd(&gsum[g * 32 + lane], val);
            atomicMax(&gmax[g * 32 + lane], ford(val));
            if (lane == 0) atomicAdd(&cnt[g], 1.f);
        }
    }
}

// --------------------------------- megakernel --------------------------------
__global__ void __launch_bounds__(512, 3)
uk(const float* __restrict__ x, const int* __restrict__ ei, const int* __restrict__ batch,
   const float* W1, const float* b1, const float* W2, const float* b2,
   const float* W3, const float* b3, const float* W4, const float* b4,
   const float* W5, const float* b5, const float* W6, const float* b6,
   const float* W7, const float* b7, const float* p1, const float* p2, const float* p3,
   const float* Wl1, const float* Wc, const float* bc, float* __restrict__ out) {
    __shared__ float sh[2176];   // GEMM tiles (<=2144 fl) / rank keys / scan
    float* B = g_ws;
    float* ZA  = B + O_ZA;
    float* ZB  = B + O_ZB;
    int*  COL  = (int*)(B + O_COL);
    int*  DEG0 = (int*)(B + O_DEG0);
    float* DV0 = B + O_DINV0;
    float* DV2 = B + O_DINV2;
    float* DV4 = B + O_DINV4;
    float* DV6 = B + O_DINV6;
    float* SS  = B + O_S;
    u64*  KEY  = (u64*)(B + O_KEY);
    int*  RANK = (int*)(B + O_RANK);
    int*  POS0 = (int*)(B + O_POS0);
    int*  POS4 = (int*)(B + O_POS4);
    int*  POS6 = (int*)(B + O_POS6);
    int*  RP   = (int*)(B + O_RP);
    int*  OFF  = (int*)(B + O_OFF);
    u32*  BM2  = (u32*)(B + O_BM2);
    u32*  BM4  = (u32*)(B + O_BM4);
    u32*  BM6  = (u32*)(B + O_BM6);
    u32*  SUM2 = (u32*)(B + O_SUM2);
    u32*  SUM4 = (u32*)(B + O_SUM4);
    u32*  SUM6 = (u32*)(B + O_SUM6);
    float* GSUM= B + O_GSUM;
    u32*  GMAX = (u32*)(B + O_GMAX);
    float* CNT = B + O_CNT;

    int tid = threadIdx.x;
    int gt  = blockIdx.x * 512 + tid;
    int NT  = gridDim.x * 512;

    // B1: degree histogram (DEG0 zero by contract) ; prologue zeroing
    for (int e = gt; e < EE; e += NT) atomicAdd(&DEG0[ei[EE + e]], 1);
    for (int i = gt; i < KK1 * NWB2; i += NT) BM2[i] = 0;
    for (int i = gt; i < NG * 32; i += NT) { GSUM[i] = 0.f; GMAX[i] = 0u; }
    for (int i = gt; i < NG; i += NT) CNT[i] = 0.f;
    zerof(ZA, NN * 32);
    zerof(ZB, KK1 * 64);
    gsync();

    // B2: block 0 CSR scan || GEMM1 splitK2 (ZA, M=32 path)
    if (blockIdx.x == 0) {
        int base = tid * 16;
        int s = 0;
#pragma unroll
        for (int j = 0; j < 16; j++) s += DEG0[base + j];
        int* shi = (int*)sh;
        shi[tid] = s;
        __syncthreads();
        for (int o = 1; o < 512; o <<= 1) {
            int v = (tid >= o) ? shi[tid - o] : 0;
            __syncthreads();
            shi[tid] += v;
            __syncthreads();
        }
        int run = shi[tid] - s;
#pragma unroll
        for (int j = 0; j < 16; j++) {
            int d = DEG0[base + j];
            RP[base + j] = run;
            OFF[base + j] = run;
            DV0[base + j] = rsqrtf((float)(d + 1));
            run += d;
        }
        if (tid == 511) RP[NN] = run;
    } else {
        gemm32_dev(x, nullptr, nullptr, 0, 0, W1, ZA, NN, 128, sh,
                   blockIdx.x - 1, gridDim.x - 1, 2);
    }
    gsync();

    // B3: CSR scatter ; re-zero DEG0
    for (int e = gt; e < EE; e += NT) {
        int s = ei[e], d = ei[EE + e];
        int pp = atomicAdd(&OFF[d], 1);
        COL[pp] = s;
    }
    for (int i = gt; i < NN; i += NT) DEG0[i] = 0;
    gsync();

    // B4: X1 = csragg(ZA) + score1/key ; zero RANK
    csragg_dev(ZA, RP, COL, DV0, b1, B + O_X1, p1, SS, KEY,
               nullptr, nullptr, nullptr, nullptr);
    for (int i = gt; i < NN; i += NT) RANK[i] = 0;
    gsync();

    // B5: rank pool1 (256 tiles)
    rank_dev(KEY, NN, 256, RANK, (u64*)sh);
    gsync();

    // B6: gather1 -> X2 ; bm_edges -> BM2 ; zero BM4
    gather_dev(B + O_X1, SS, RANK, NN, KK1, 32, B + O_X2, POS0);
    for (int e = gt; e < EE; e += NT) {
        int rs = RANK[ei[e]], rd = RANK[ei[EE + e]];
        if (rs < KK1 && rd < KK1)
            atomicOr(&BM2[(size_t)rd * NWB2 + (rs >> 5)], 1u << (rs & 31));
    }
    for (int i = gt; i < KK2 * NWB4; i += NT) BM4[i] = 0;
    gsync();

    // B7: GEMM2 splitK2 (ZB) || dinvsum2
    gemm64_dev(B + O_X2, nullptr, nullptr, 0, 0, W2, ZB, KK1, 32, 64, sh,
               blockIdx.x, gridDim.x, 2);
    dinvsum_dev(BM2, KK1, NWB2, NSW2, DV2, SUM2);
    gsync();

    // B8: spmm2(ZB) -> X3 + score2 ; zero RANK ; zero ZA (GEMM3)
    spmm_dev<2, 1>(BM2, SUM2, NWB2, NSW2, ZB, DV2, b2, B + O_X3, KK1, p2, SS, KEY);
    for (int i = gt; i < KK1; i += NT) RANK[i] = 0;
    zerof(ZA, KK2 * 128);
    gsync();

    // B9: rank pool2 (256 tiles)
    rank_dev(KEY, KK1, 64, RANK, (u64*)sh);
    gsync();

    // B10: gather2 -> X4 ; bmfilter BM2->BM4 ; zero BM6
    gather_dev(B + O_X3, SS, RANK, KK1, KK2, 64, B + O_X4, POS4);
    bmfilter_dev(BM2, SUM2, NWB2, NSW2, KK1, RANK, KK2, NWB4, BM4);
    for (int i = gt; i < KK3 * NWB6; i += NT) BM6[i] = 0;
    gsync();

    // B11: GEMM3 splitK4 (ZA) || dinvsum4
    gemm64_dev(B + O_X4, nullptr, nullptr, 0, 0, W3, ZA, KK2, 64, 128, sh,
               blockIdx.x, gridDim.x, 4);
    dinvsum_dev(BM4, KK2, NWB4, NSW4, DV4, SUM4);
    gsync();

    // B12: spmm3(ZA) -> X5 + score3 ; zero RANK ; zero ZB (GEMM4)
    spmm_dev<4, 1>(BM4, SUM4, NWB4, NSW4, ZA, DV4, b3, B + O_X5, KK2, p3, SS, KEY);
    for (int i = gt; i < KK2; i += NT) RANK[i] = 0;
    zerof(ZB, KK3 * 256);
    gsync();

    // B13: rank pool3 (64 tiles)
    rank_dev(KEY, KK2, 64, RANK, (u64*)sh);
    gsync();

    // B14: gather3 -> X6 ; bmfilter BM4->BM6
    gather_dev(B + O_X5, SS, RANK, KK2, KK3, 128, B + O_X6, POS6);
    bmfilter_dev(BM4, SUM4, NWB4, NSW4, KK2, RANK, KK3, NWB6, BM6);
    gsync();

    // B15: GEMM4 splitK4 (ZB) || dinvsum6
    gemm64_dev(B + O_X6, nullptr, nullptr, 0, 0, W4, ZB, KK3, 128, 256, sh,
               blockIdx.x, gridDim.x, 4);
    dinvsum_dev(BM6, KK3, NWB6, NSW6, DV6, SUM6);
    gsync();

    // B16: spmm4(ZB) -> X7 (2 col-segments/row) ; zero ZA (GEMM5)
    spmm_dev<4, 2>(BM6, SUM6, NWB6, NSW6, ZB, DV6, b4, B + O_X7, KK3,
                   nullptr, nullptr, nullptr);
    zerof(ZA, KK2 * 128);
    gsync();

    // B17: GEMM5 splitK4 (ZA) fused concat(X7 via POS6, skip X5)
    gemm64_dev(B + O_X7, POS6, B + O_X5, 256, 128, W5, ZA, KK2, 384, 128, sh,
               blockIdx.x, gridDim.x, 4);
    gsync();

    // B18: spmm5(ZA) -> X9 ; zero ZB (GEMM6)
    spmm_dev<4, 1>(BM4, SUM4, NWB4, NSW4, ZA, DV4, b5, B + O_X9, KK2,
                   nullptr, nullptr, nullptr);
    zerof(ZB, KK1 * 64);
    gsync();

    // B19: GEMM6 splitK4 (ZB) fused concat(X9 via POS4, skip X3)
    gemm64_dev(B + O_X9, POS4, B + O_X3, 128, 64, W6, ZB, KK1, 192, 64, sh,
               blockIdx.x, gridDim.x, 4);
    gsync();

    // B20: spmm6(ZB) -> X11 ; zero ZA (GEMM7)
    spmm_dev<2, 1>(BM2, SUM2, NWB2, NSW2, ZB, DV2, b6, B + O_X11, KK1,
                   nullptr, nullptr, nullptr);
    zerof(ZA, NN * 32);
    gsync();

    // B21: GEMM7 splitK2 (ZA, M=32 path) fused concat(X11 via POS0, skip X1)
    gemm32_dev(B + O_X11, POS0, B + O_X1, 64, 32, W7, ZA, NN, 96, sh,
               blockIdx.x, gridDim.x, 2);
    gsync();

    // B22: final csragg(ZA) with fused readout
    csragg_dev(ZA, RP, COL, DV0, b7, nullptr, nullptr, nullptr, nullptr,
               batch, GSUM, GMAX, CNT);
    gsync();

    // ---- head ----
    if (blockIdx.x < NG) {
        int g = blockIdx.x;
        float* h  = sh;
        float* h2 = sh + 64;
        float* lg = sh + 128;
        if (tid < 64)
            h[tid] = eluf(tid < 32 ? unford(GMAX[g * 32 + tid])
                                   : GSUM[g * 32 + (tid - 32)] / CNT[g]);
        __syncthreads();
        if (tid < 64) {
            float acc = 0.f;
#pragma unroll
            for (int k = 0; k < 64; k++) acc += h[k] * Wl1[k * 64 + tid];
            h2[tid] = eluf(acc);
        }
        __syncthreads();
        if (tid < 10) {
            float a = bc[tid];
#pragma unroll
            for (int k = 0; k < 64; k++) a += h2[k] * Wc[k * 10 + tid];
            lg[tid] = a;
        }
        __syncthreads();
        if (tid == 0) {
            float m = lg[0];
            for (int c = 1; c < 10; c++) m = fmaxf(m, lg[c]);
            float se = 0.f;
            for (int c = 0; c < 10; c++) se += expf(lg[c] - m);
            sh[140] = m + logf(se);
        }
        __syncthreads();
        if (tid < 10) out[g * 10 + tid] = lg[tid] - sh[140];
    }
}

// ------------------------------- launcher ------------------------------------
extern "C" void kernel_launch(void* const* d_in, const int* in_sizes, int n_in,
                              void* d_out, int out_size) {
    (void)in_sizes; (void)n_in; (void)out_size;
    const float* x    = (const float*)d_in[0];
    const int*   ei   = (const int*)d_in[1];
    const int*   batch= (const int*)d_in[2];
    const float* W1 = (const float*)d_in[3],  *b1 = (const float*)d_in[4];
    const float* W2 = (const float*)d_in[5],  *b2 = (const float*)d_in[6];
    const float* W3 = (const float*)d_in[7],  *b3 = (const float*)d_in[8];
    const float* W4 = (const float*)d_in[9],  *b4 = (const float*)d_in[10];
    const float* W5 = (const float*)d_in[11], *b5 = (const float*)d_in[12];
    const float* W6 = (const float*)d_in[13], *b6 = (const float*)d_in[14];
    const float* W7 = (const float*)d_in[15], *b7 = (const float*)d_in[16];
    const float* p1 = (const float*)d_in[17];
    const float* p2 = (const float*)d_in[18];
    const float* p3 = (const float*)d_in[19];
    const float* Wl1= (const float*)d_in[20];
    const float* Wc = (const float*)d_in[21];
    const float* bc = (const float*)d_in[22];
    float* out = (float*)d_out;

    int dev = 0;
    cudaGetDevice(&dev);
    int nsm = 148;
    cudaDeviceGetAttribute(&nsm, cudaDevAttrMultiProcessorCount, dev);

    uk<<<nsm * 3, 512>>>(x, ei, batch, W1, b1, W2, b2, W3, b3, W4, b4,
                         W5, b5, W6, b6, W7, b7, p1, p2, p3, Wl1, Wc, bc, out);
}

// round 14
// speedup vs baseline: 1.2144x; 1.2144x over previous
#include <cuda_runtime.h>
#include <math.h>

#define NN 8192
#define EE 262144
#define KK1 4096
#define KK2 2048
#define KK3 1024
#define NG 64

typedef unsigned int u32;
typedef unsigned long long u64;

constexpr int NWB2 = KK1 / 32;
constexpr int NWB4 = KK2 / 32;
constexpr int NWB6 = KK3 / 32;
constexpr int NSW2 = NWB2 / 32;
constexpr int NSW4 = NWB4 / 32;
constexpr int NSW6 = NWB6 / 32;

// ------------------------- workspace layout (float units) --------------------
constexpr size_t O_X1   = 0;                 constexpr size_t S_X1   = (size_t)NN*32;
constexpr size_t O_X2   = O_X1+S_X1;         constexpr size_t S_X2   = (size_t)KK1*32;
constexpr size_t O_X3   = O_X2+S_X2;         constexpr size_t S_X3   = (size_t)KK1*64;
constexpr size_t O_X4   = O_X3+S_X3;         constexpr size_t S_X4   = (size_t)KK2*64;
constexpr size_t O_X5   = O_X4+S_X4;         constexpr size_t S_X5   = (size_t)KK2*128;
constexpr size_t O_X6   = O_X5+S_X5;         constexpr size_t S_X6   = (size_t)KK3*128;
constexpr size_t O_X7   = O_X6+S_X6;         constexpr size_t S_X7   = (size_t)KK3*256;
constexpr size_t O_X9   = O_X7+S_X7;         constexpr size_t S_X9   = (size_t)KK2*128;
constexpr size_t O_X11  = O_X9+S_X9;         constexpr size_t S_X11  = (size_t)KK1*64;
constexpr size_t O_ZA   = O_X11+S_X11;       constexpr size_t S_ZA   = 262144;
constexpr size_t O_ZB   = O_ZA+S_ZA;         constexpr size_t S_ZB   = 262144;
constexpr size_t O_COL  = O_ZB+S_ZB;         constexpr size_t S_COL  = EE;
constexpr size_t O_DEG0 = O_COL+S_COL;       constexpr size_t S_DEG0 = NN;
constexpr size_t O_DINV0= O_DEG0+S_DEG0;     constexpr size_t S_DINV0= NN;
constexpr size_t O_DINV2= O_DINV0+S_DINV0;   constexpr size_t S_DINV2= KK1;
constexpr size_t O_DINV4= O_DINV2+S_DINV2;   constexpr size_t S_DINV4= KK2;
constexpr size_t O_DINV6= O_DINV4+S_DINV4;   constexpr size_t S_DINV6= KK3;
constexpr size_t O_S    = O_DINV6+S_DINV6;   constexpr size_t S_S    = NN;
constexpr size_t O_KEY  = O_S+S_S;           constexpr size_t S_KEY  = (size_t)NN*2;
constexpr size_t O_RANK = O_KEY+S_KEY;       constexpr size_t S_RANK = NN;
constexpr size_t O_POS0 = O_RANK+S_RANK;     constexpr size_t S_POS0 = NN;
constexpr size_t O_POS4 = O_POS0+S_POS0;     constexpr size_t S_POS4 = KK1;
constexpr size_t O_POS6 = O_POS4+S_POS4;     constexpr size_t S_POS6 = KK2;
constexpr size_t O_RP   = O_POS6+S_POS6;     constexpr size_t S_RP   = NN+8;
constexpr size_t O_OFF  = O_RP+S_RP;         constexpr size_t S_OFF  = NN;
constexpr size_t O_BM2  = O_OFF+S_OFF;       constexpr size_t S_BM2  = (size_t)KK1*NWB2;
constexpr size_t O_BM4  = O_BM2+S_BM2;       constexpr size_t S_BM4  = (size_t)KK2*NWB4;
constexpr size_t O_BM6  = O_BM4+S_BM4;       constexpr size_t S_BM6  = (size_t)KK3*NWB6;
constexpr size_t O_SUM2 = O_BM6+S_BM6;       constexpr size_t S_SUM2 = (size_t)KK1*NSW2;
constexpr size_t O_SUM4 = O_SUM2+S_SUM2;     constexpr size_t S_SUM4 = (size_t)KK2*NSW4;
constexpr size_t O_SUM6 = O_SUM4+S_SUM4;     constexpr size_t S_SUM6 = (size_t)KK3*NSW6;
constexpr size_t O_GSUM = O_SUM6+S_SUM6;     constexpr size_t S_GSUM = (size_t)NG*32;
constexpr size_t O_GMAX = O_GSUM+S_GSUM;     constexpr size_t S_GMAX = (size_t)NG*32;
constexpr size_t O_CNT  = O_GMAX+S_GMAX;     constexpr size_t S_CNT  = NG;
constexpr size_t WS_TOTAL = O_CNT + S_CNT;

__device__ __align__(256) float g_ws[WS_TOTAL];
__device__ unsigned g_arrive = 0;

// ------------------------------- helpers -------------------------------------
__device__ __forceinline__ float eluf(float x) { return x > 0.f ? x : expm1f(x); }
__device__ __forceinline__ unsigned ford(float f) {
    unsigned u = __float_as_uint(f);
    return (u & 0x80000000u) ? ~u : (u | 0x80000000u);
}
__device__ __forceinline__ float unford(unsigned u) {
    return __uint_as_float((u & 0x80000000u) ? (u & 0x7fffffffu) : ~u);
}

// chip-wide barrier: release-arrive / acquire-spin (1 block/SM)  [R8/R11]
__device__ __forceinline__ void gsync() {
    __syncthreads();
    if (threadIdx.x == 0) {
        unsigned t;
        asm volatile("atom.release.gpu.add.u32 %0, [%1], 1;"
                     : "=r"(t) : "l"(&g_arrive) : "memory");
        unsigned target = (t / gridDim.x + 1u) * gridDim.x;
        unsigned v;
        do {
            asm volatile("ld.acquire.gpu.u32 %0, [%1];"
                         : "=r"(v) : "l"(&g_arrive) : "memory");
        } while (v < target);
    }
    __syncthreads();
}

__device__ __forceinline__ void zerof(float* p, int n) {
    int gt = blockIdx.x * blockDim.x + threadIdx.x, NT = gridDim.x * blockDim.x;
    for (int i = gt; i < n; i += NT) p[i] = 0.f;
}

// ---------------------------- phase device funcs ------------------------------

__device__ __forceinline__ float a_elem(const float* __restrict__ X,
                                        const int* __restrict__ pos,
                                        const float* __restrict__ skip,
                                        int F1, int F2, int K, int gi, int kk) {
    if (!pos) return X[(size_t)gi * K + kk];
    if (kk < F1) {
        int p = pos[gi];
        return (p >= 0) ? eluf(X[(size_t)p * F1 + kk]) : 0.f;
    }
    return eluf(skip[(size_t)gi * F2 + (kk - F1)]);
}

// 128x64-tile GEMM, 1024 threads, 4x2 micro; double-buffered smem (1 sync/slab);
// split-K atomicAdd accumulate.
constexpr int GBUF = 16 * 132 + 16 * 66;   // 3168 floats per buffer
__device__ void gemm_dev(const float* __restrict__ X, const int* __restrict__ pos,
                         const float* __restrict__ skip, int F1, int F2,
                         const float* __restrict__ W, float* __restrict__ out,
                         int n, int K, int M, float* sh, int bstart, int bstride,
                         int SK) {
    int tid = threadIdx.x;
    int tm = (tid >> 5) << 2;
    int tn = (tid & 31) << 1;
    int m0 = tid >> 4, kA = tid & 15;
    int bk = tid >> 6, bj = tid & 63;
    int ntn = (M + 63) >> 6;
    int ntm = n >> 7;
    int ntile = ntm * ntn;
    int njobs = ntile * SK;
    int Kb = K / SK;
    for (int j = bstart; j < njobs; j += bstride) {
        int t = j % ntile, kh = j / ntile;
        int kbeg = kh * Kb, kend = kbeg + Kb;
        int bm = (t / ntn) << 7, bn = (t % ntn) << 6;
        float acc[4][2];
#pragma unroll
        for (int r = 0; r < 4; r++) { acc[r][0] = 0.f; acc[r][1] = 0.f; }
        float ra0 = a_elem(X, pos, skip, F1, F2, K, bm + m0, kbeg + kA);
        float ra1 = a_elem(X, pos, skip, F1, F2, K, bm + m0 + 64, kbeg + kA);
        float rb  = (bn + bj < M) ? W[(size_t)(kbeg + bk) * M + (bn + bj)] : 0.f;
        int cur = 0;
        __syncthreads();   // all readers of previous job's smem are done
        for (int kk = kbeg; kk < kend; kk += 16) {
            float* As = sh + cur * GBUF;
            float* Bs = As + 16 * 132;
            As[kA * 132 + m0] = ra0;
            As[kA * 132 + m0 + 64] = ra1;
            Bs[bk * 66 + bj] = rb;
            __syncthreads();
            if (kk + 16 < kend) {
                ra0 = a_elem(X, pos, skip, F1, F2, K, bm + m0, kk + 16 + kA);
                ra1 = a_elem(X, pos, skip, F1, F2, K, bm + m0 + 64, kk + 16 + kA);
                rb  = (bn + bj < M) ? W[(size_t)(kk + 16 + bk) * M + (bn + bj)] : 0.f;
            }
#pragma unroll
            for (int k = 0; k < 16; k++) {
                float4 aa = *(const float4*)&As[k * 132 + tm];
                float2 bb = *(const float2*)&Bs[k * 66 + tn];
                acc[0][0] += aa.x * bb.x; acc[0][1] += aa.x * bb.y;
                acc[1][0] += aa.y * bb.x; acc[1][1] += aa.y * bb.y;
                acc[2][0] += aa.z * bb.x; acc[2][1] += aa.z * bb.y;
                acc[3][0] += aa.w * bb.x; acc[3][1] += aa.w * bb.y;
            }
            cur ^= 1;
        }
        int gi = bm + tm, gj = bn + tn;
        if (gj < M) {
#pragma unroll
            for (int r = 0; r < 4; r++)
                atomicAdd(&out[(size_t)(gi + r) * M + gj], acc[r][0]);
            if (gj + 1 < M) {
#pragma unroll
                for (int r = 0; r < 4; r++)
                    atomicAdd(&out[(size_t)(gi + r) * M + gj + 1], acc[r][1]);
            }
        }
    }
}

// 128x32-tile GEMM for M==32, 1024 threads, 4x1 micro; double-buffered smem.
constexpr int GBUF32 = 16 * 132 + 16 * 33;   // 2640 floats per buffer
__device__ void gemm32_dev(const float* __restrict__ X, const int* __restrict__ pos,
                           const float* __restrict__ skip, int F1, int F2,
                           const float* __restrict__ W, float* __restrict__ out,
                           int n, int K, float* sh, int bstart, int bstride,
                           int SK) {
    int tid = threadIdx.x;
    int tm = (tid >> 5) << 2;
    int tn = tid & 31;
    int m0 = tid >> 4, kA = tid & 15;
    int bk = tid >> 5, bj = tid & 31;   // tid<512 loads Bs (16x32)
    int ntm = n >> 7;
    int njobs = ntm * SK;
    int Kb = K / SK;
    for (int j = bstart; j < njobs; j += bstride) {
        int t = j % ntm, kh = j / ntm;
        int kbeg = kh * Kb, kend = kbeg + Kb;
        int bm = t << 7;
        float a0 = 0.f, a1 = 0.f, a2 = 0.f, a3 = 0.f;
        float ra0 = a_elem(X, pos, skip, F1, F2, K, bm + m0, kbeg + kA);
        float ra1 = a_elem(X, pos, skip, F1, F2, K, bm + m0 + 64, kbeg + kA);
        float rb  = (tid < 512) ? W[(size_t)(kbeg + bk) * 32 + bj] : 0.f;
        int cur = 0;
        __syncthreads();
        for (int kk = kbeg; kk < kend; kk += 16) {
            float* As = sh + cur * GBUF32;
            float* Bs = As + 16 * 132;
            As[kA * 132 + m0] = ra0;
            As[kA * 132 + m0 + 64] = ra1;
            if (tid < 512) Bs[bk * 33 + bj] = rb;
            __syncthreads();
            if (kk + 16 < kend) {
                ra0 = a_elem(X, pos, skip, F1, F2, K, bm + m0, kk + 16 + kA);
                ra1 = a_elem(X, pos, skip, F1, F2, K, bm + m0 + 64, kk + 16 + kA);
                rb  = (tid < 512) ? W[(size_t)(kk + 16 + bk) * 32 + bj] : 0.f;
            }
#pragma unroll
            for (int k = 0; k < 16; k++) {
                float4 aa = *(const float4*)&As[k * 132 + tm];
                float b  = Bs[k * 33 + tn];
                a0 += aa.x * b; a1 += aa.y * b;
                a2 += aa.z * b; a3 += aa.w * b;
            }
            cur ^= 1;
        }
        int gi = bm + tm;
        atomicAdd(&out[(size_t)gi * 32 + tn], a0);
        atomicAdd(&out[(size_t)(gi + 1) * 32 + tn], a1);
        atomicAdd(&out[(size_t)(gi + 2) * 32 + tn], a2);
        atomicAdd(&out[(size_t)(gi + 3) * 32 + tn], a3);
    }
}

// 64x64-tile GEMM, 1024 threads, 2x2 micro; double-buffered smem.
constexpr int GBUF64 = 16 * 66 + 16 * 66;   // 2112 floats per buffer
__device__ void gemm64_dev(const float* __restrict__ X,
                           const float* __restrict__ W, float* __restrict__ out,
                           int n, int K, int M, float* sh, int bstart, int bstride,
                           int SK) {
    int tid = threadIdx.x;
    int tm = (tid >> 5) << 1;
    int tn = (tid & 31) << 1;
    int lm = tid >> 4, lk = tid & 15;
    int bk = tid >> 6, bj = tid & 63;
    int ntn = (M + 63) >> 6;
    int ntm = n >> 6;
    int ntile = ntm * ntn;
    int njobs = ntile * SK;
    int Kb = K / SK;
    for (int j = bstart; j < njobs; j += bstride) {
        int t = j % ntile, kh = j / ntile;
        int kbeg = kh * Kb, kend = kbeg + Kb;
        int bm = (t / ntn) << 6, bn = (t % ntn) << 6;
        float a00 = 0.f, a01 = 0.f, a10 = 0.f, a11 = 0.f;
        float ra = X[(size_t)(bm + lm) * K + (kbeg + lk)];
        float rb = (bn + bj < M) ? W[(size_t)(kbeg + bk) * M + (bn + bj)] : 0.f;
        int cur = 0;
        __syncthreads();
        for (int kk = kbeg; kk < kend; kk += 16) {
            float* As = sh + cur * GBUF64;
            float* Bs = As + 16 * 66;
            As[lk * 66 + lm] = ra;
            Bs[bk * 66 + bj] = rb;
            __syncthreads();
            if (kk + 16 < kend) {
                ra = X[(size_t)(bm + lm) * K + (kk + 16 + lk)];
                rb = (bn + bj < M) ? W[(size_t)(kk + 16 + bk) * M + (bn + bj)] : 0.f;
            }
#pragma unroll
            for (int k = 0; k < 16; k++) {
                float2 aa = *(const float2*)&As[k * 66 + tm];
                float2 bb = *(const float2*)&Bs[k * 66 + tn];
                a00 += aa.x * bb.x; a01 += aa.x * bb.y;
                a10 += aa.y * bb.x; a11 += aa.y * bb.y;
            }
            cur ^= 1;
        }
        int gi = bm + tm, gj = bn + tn;
        if (gj < M) {
            atomicAdd(&out[(size_t)gi * M + gj], a00);
            atomicAdd(&out[(size_t)(gi + 1) * M + gj], a10);
            if (gj + 1 < M) {
                atomicAdd(&out[(size_t)gi * M + gj + 1], a01);
                atomicAdd(&out[(size_t)(gi + 1) * M + gj + 1], a11);
            }
        }
    }
}

// rank: 2048-row i-tiles, 2 rows per thread; CH-wide j-chunks in smem  [R11]
__device__ void rank_dev(const u64* __restrict__ key, int n, int CH,
                         int* __restrict__ rank, u64* shk) {
    int nti = n >> 11;
    int ntj = n / CH;
    for (int t = blockIdx.x; t < nti * ntj; t += gridDim.x) {
        int ti = t / ntj, tj = t - ti * ntj;
        int i0 = (ti << 11) + threadIdx.x;
        int j0 = tj * CH;
        __syncthreads();
        for (int l = threadIdx.x; l < CH; l += 1024) shk[l] = key[j0 + l];
        __syncthreads();
        u64 ka = key[i0], kb = key[i0 + 1024];
        int ca = 0, cb = 0;
#pragma unroll 8
        for (int j = 0; j < CH; j++) {
            u64 kj = shk[j];
            ca += (kj > ka) ? 1 : 0;
            cb += (kj > kb) ? 1 : 0;
        }
        if (ca) atomicAdd(&rank[i0], ca);
        if (cb) atomicAdd(&rank[i0 + 1024], cb);
    }
}

__device__ void gather_dev(const float* __restrict__ x, const float* __restrict__ s,
                           const int* __restrict__ rank, int n, int k, int F,
                           float* __restrict__ out, int* __restrict__ pos) {
    int gt = blockIdx.x * blockDim.x + threadIdx.x, NT = gridDim.x * blockDim.x;
    for (int t = gt; t < n * F; t += NT) {
        int i = t / F, f = t - i * F;
        int r = rank[i];
        if (f == 0) pos[i] = (r < k) ? r : -1;
        if (r < k) {
            float gate = 1.f / (1.f + expf(-s[i]));
            out[(size_t)r * F + f] = eluf(x[t] * gate);
        }
    }
}

__device__ void bmfilter_dev(const u32* __restrict__ bms, const u32* __restrict__ ssum,
                             int nws, int nssw, int nsrc, const int* __restrict__ rank,
                             int k, int nwd, u32* __restrict__ bmd) {
    int lane = threadIdx.x & 31;
    int wg = (blockIdx.x * blockDim.x + threadIdx.x) >> 5;
    int NWp = (gridDim.x * blockDim.x) >> 5;
    for (int i = wg; i < nsrc; i += NWp) {
        int b = rank[i];
        if (b >= k) continue;
        const u32* row = bms + (size_t)i * nws;
        const u32* srow = ssum + (size_t)i * nssw;
        for (int w = lane; w < nws; w += 32) {
            if (!((srow[w >> 5] >> (w & 31)) & 1u)) continue;
            u32 word = row[w];
            while (word) {
                int bit = __ffs(word) - 1; word &= word - 1;
                int ps = rank[(w << 5) + bit];
                if (ps < k) atomicOr(&bmd[(size_t)b * nwd + (ps >> 5)], 1u << (ps & 31));
            }
        }
    }
}

__device__ void dinvsum_dev(const u32* __restrict__ bm, int n, int nw, int nsw,
                            float* __restrict__ dv, u32* __restrict__ sum) {
    int lane = threadIdx.x & 31;
    int wg = (blockIdx.x * blockDim.x + threadIdx.x) >> 5;
    int NWp = (gridDim.x * blockDim.x) >> 5;
    for (int r = wg; r < n; r += NWp) {
        int c = 0;
        for (int g = 0; g < nsw; g++) {
            u32 word = bm[(size_t)r * nw + (g << 5) + lane];
            u32 m = __ballot_sync(0xffffffffu, word != 0u);
            c += __popc(word);
            if (lane == 0) sum[(size_t)r * nsw + g] = m;
        }
#pragma unroll
        for (int o = 16; o > 0; o >>= 1) c += __shfl_xor_sync(0xffffffffu, c, o);
        if (lane == 0) dv[r] = rsqrtf((float)(c + 1));
    }
}

// bitmap SpMM; neighbors batch-decoded (NB at a time) for MLP.  [R11]
template<int FW>
__device__ void spmm_dev(const u32* __restrict__ bm, const u32* __restrict__ sum,
                         int nw, int nsw, const float* __restrict__ z,
                         const float* __restrict__ dv, const float* __restrict__ bias,
                         float* __restrict__ out, int n,
                         const float* __restrict__ p, float* __restrict__ ss,
                         u64* __restrict__ key) {
    const int F = FW * 32;
    const int NB = (FW <= 4) ? 4 : 2;
    int lane = threadIdx.x & 31;
    int wg = (blockIdx.x * blockDim.x + threadIdx.x) >> 5;
    int NWp = (gridDim.x * blockDim.x) >> 5;
    float bl[FW], pl[FW];
#pragma unroll
    for (int c = 0; c < FW; c++) bl[c] = bias[lane + 32 * c];
    float invn = 0.f;
    if (p) {
        float q = 0.f;
#pragma unroll
        for (int c = 0; c < FW; c++) { pl[c] = p[lane + 32 * c]; q += pl[c] * pl[c]; }
#pragma unroll
        for (int o = 16; o > 0; o >>= 1) q += __shfl_xor_sync(0xffffffffu, q, o);
        invn = rsqrtf(q);
    }
    for (int r = wg; r < n; r += NWp) {
        float dr = dv[r];
        float acc[FW];
#pragma unroll
        for (int c = 0; c < FW; c++) acc[c] = dr * z[(size_t)r * F + lane + 32 * c];
        const u32* row = bm + (size_t)r * nw;
        const u32* srow = sum + (size_t)r * nsw;
        int nbuf[NB];
        int m = 0;
        auto flush = [&](int mc) {
            float dvs[NB];
            float tmp[NB][FW];
#pragma unroll
            for (int i = 0; i < NB; i++) if (i < mc) dvs[i] = dv[nbuf[i]];
#pragma unroll
            for (int i = 0; i < NB; i++) if (i < mc) {
                const float* zs = z + (size_t)nbuf[i] * F + lane;
#pragma unroll
                for (int c = 0; c < FW; c++) tmp[i][c] = zs[32 * c];
            }
#pragma unroll
            for (int i = 0; i < NB; i++) if (i < mc)
#pragma unroll
                for (int c = 0; c < FW; c++) acc[c] += dvs[i] * tmp[i][c];
        };
        for (int sw = 0; sw < nsw; sw++) {
            u32 sword = srow[sw];
            while (sword) {
                int wb = __ffs(sword) - 1; sword &= sword - 1;
                int w = (sw << 5) + wb;
                u32 word = row[w];
                while (word) {
                    int b = __ffs(word) - 1; word &= word - 1;
                    nbuf[m++] = (w << 5) + b;
                    if (m == NB) { flush(NB); m = 0; }
                }
            }
        }
        if (m) flush(m);
        float sc = 0.f;
#pragma unroll
        for (int c = 0; c < FW; c++) {
            float v = eluf(dr * acc[c] + bl[c]);
            out[(size_t)r * F + lane + 32 * c] = v;
            if (p) sc += v * pl[c];
        }
        if (p) {
#pragma unroll
            for (int o = 16; o > 0; o >>= 1) sc += __shfl_xor_sync(0xffffffffu, sc, o);
            if (lane == 0) {
                float sv = sc * invn;
                ss[r] = sv;
                key[r] = ((u64)ford(sv) << 32) | (u32)(~r);
            }
        }
    }
}

__device__ void csragg_dev(const float* __restrict__ z, const int* __restrict__ rp,
                           const int* __restrict__ col, const float* __restrict__ dv,
                           const float* __restrict__ bias, float* __restrict__ out,
                           const float* __restrict__ p, float* __restrict__ ss,
                           u64* __restrict__ key,
                           const int* __restrict__ batch, float* __restrict__ gsum,
                           u32* __restrict__ gmax, float* __restrict__ cnt) {
    int lane = threadIdx.x & 31;
    int wg = (blockIdx.x * blockDim.x + threadIdx.x) >> 5;
    int NWp = (gridDim.x * blockDim.x) >> 5;
    float invn = 0.f, pv = 0.f;
    if (p) {
        pv = p[lane];
        float q = pv * pv;
#pragma unroll
        for (int o = 16; o > 0; o >>= 1) q += __shfl_xor_sync(0xffffffffu, q, o);
        invn = rsqrtf(q);
    }
    float bl = bias[lane];
    for (int r = wg; r < NN; r += NWp) {
        float dr = dv[r];
        float acc = dr * z[r * 32 + lane];
        int e = rp[r], e1 = rp[r + 1];
        for (; e + 7 < e1; e += 8) {
            int s[8]; float d[8], v[8];
#pragma unroll
            for (int i = 0; i < 8; i++) s[i] = col[e + i];
#pragma unroll
            for (int i = 0; i < 8; i++) { d[i] = dv[s[i]]; v[i] = z[s[i] * 32 + lane]; }
#pragma unroll
            for (int i = 0; i < 8; i++) acc += d[i] * v[i];
        }
        for (; e < e1; e++) { int s = col[e]; acc += dv[s] * z[s * 32 + lane]; }
        float val = eluf(dr * acc + bl);
        if (out) {
            out[r * 32 + lane] = val;
            if (p) {
                float sc = val * pv;
#pragma unroll
                for (int o = 16; o > 0; o >>= 1) sc += __shfl_xor_sync(0xffffffffu, sc, o);
                if (lane == 0) {
                    float sv = sc * invn;
                    ss[r] = sv;
                    key[r] = ((u64)ford(sv) << 32) | (u32)(~r);
                }
            }
        } else {
            int g = batch[r];
            atomicAdd(&gsum[g * 32 + lane], val);
            atomicMax(&gmax[g * 32 + lane], ford(val));
            if (lane == 0) atomicAdd(&cnt[g], 1.f);
        }
    }
}

// --------------------------------- megakernel --------------------------------
__global__ void __launch_bounds__(1024, 1)
uk(const float* __restrict__ x, const int* __restrict__ ei, const int* __restrict__ batch,
   const float* W1, const float* b1, const float* W2, const float* b2,
   const float* W3, const float* b3, const float* W4, const float* b4,
   const float* W5, const float* b5, const float* W6, const float* b6,
   const float* W7, const float* b7, const float* p1, const float* p2, const float* p3,
   const float* Wl1, const float* Wc, const float* bc, float* __restrict__ out) {
    __shared__ float sh[6400];   // 2x3168 GEMM double-buffer (+pad); rank/scan/head reuse
    float* B = g_ws;
    float* ZA  = B + O_ZA;
    float* ZB  = B + O_ZB;
    int*  COL  = (int*)(B + O_COL);
    int*  DEG0 = (int*)(B + O_DEG0);
    float* DV0 = B + O_DINV0;
    float* DV2 = B + O_DINV2;
    float* DV4 = B + O_DINV4;
    float* DV6 = B + O_DINV6;
    float* SS  = B + O_S;
    u64*  KEY  = (u64*)(B + O_KEY);
    int*  RANK = (int*)(B + O_RANK);
    int*  POS0 = (int*)(B + O_POS0);
    int*  POS4 = (int*)(B + O_POS4);
    int*  POS6 = (int*)(B + O_POS6);
    int*  RP   = (int*)(B + O_RP);
    int*  OFF  = (int*)(B + O_OFF);
    u32*  BM2  = (u32*)(B + O_BM2);
    u32*  BM4  = (u32*)(B + O_BM4);
    u32*  BM6  = (u32*)(B + O_BM6);
    u32*  SUM2 = (u32*)(B + O_SUM2);
    u32*  SUM4 = (u32*)(B + O_SUM4);
    u32*  SUM6 = (u32*)(B + O_SUM6);
    float* GSUM= B + O_GSUM;
    u32*  GMAX = (u32*)(B + O_GMAX);
    float* CNT = B + O_CNT;

    int tid = threadIdx.x;
    int gt  = blockIdx.x * 1024 + tid;
    int NT  = gridDim.x * 1024;

    // B1: degree histogram (DEG0 zero by contract) ; prologue zeroing
    for (int e = gt; e < EE; e += NT) atomicAdd(&DEG0[ei[EE + e]], 1);
    for (int i = gt; i < KK1 * NWB2; i += NT) BM2[i] = 0;
    for (int i = gt; i < NG * 32; i += NT) { GSUM[i] = 0.f; GMAX[i] = 0u; }
    for (int i = gt; i < NG; i += NT) CNT[i] = 0.f;
    zerof(ZA, NN * 32);
    zerof(ZB, KK1 * 64);
    gsync();

    // B2: block 0 CSR scan || GEMM1 splitK2 (ZA, M=32 path)
    if (blockIdx.x == 0) {
        int base = tid * 8;
        int s = 0;
#pragma unroll
        for (int j = 0; j < 8; j++) s += DEG0[base + j];
        int* shi = (int*)sh;
        shi[tid] = s;
        __syncthreads();
        for (int o = 1; o < 1024; o <<= 1) {
            int v = (tid >= o) ? shi[tid - o] : 0;
            __syncthreads();
            shi[tid] += v;
            __syncthreads();
        }
        int run = shi[tid] - s;
#pragma unroll
        for (int j = 0; j < 8; j++) {
            int d = DEG0[base + j];
            RP[base + j] = run;
            OFF[base + j] = run;
            DV0[base + j] = rsqrtf((float)(d + 1));
            run += d;
        }
        if (tid == 1023) RP[NN] = run;
    } else {
        gemm32_dev(x, nullptr, nullptr, 0, 0, W1, ZA, NN, 128, sh,
                   blockIdx.x - 1, gridDim.x - 1, 2);
    }
    gsync();

    // B3: CSR scatter ; re-zero DEG0
    for (int e = gt; e < EE; e += NT) {
        int s = ei[e], d = ei[EE + e];
        int pp = atomicAdd(&OFF[d], 1);
        COL[pp] = s;
    }
    for (int i = gt; i < NN; i += NT) DEG0[i] = 0;
    gsync();

    // B4: X1 = csragg(ZA) + score1/key ; zero RANK
    csragg_dev(ZA, RP, COL, DV0, b1, B + O_X1, p1, SS, KEY,
               nullptr, nullptr, nullptr, nullptr);
    for (int i = gt; i < NN; i += NT) RANK[i] = 0;
    gsync();

    // B5: rank pool1 (128 tiles)
    rank_dev(KEY, NN, 256, RANK, (u64*)sh);
    gsync();

    // B6: gather1 -> X2 ; bm_edges -> BM2 ; zero BM4
    gather_dev(B + O_X1, SS, RANK, NN, KK1, 32, B + O_X2, POS0);
    for (int e = gt; e < EE; e += NT) {
        int rs = RANK[ei[e]], rd = RANK[ei[EE + e]];
        if (rs < KK1 && rd < KK1)
            atomicOr(&BM2[(size_t)rd * NWB2 + (rs >> 5)], 1u << (rs & 31));
    }
    for (int i = gt; i < KK2 * NWB4; i += NT) BM4[i] = 0;
    gsync();

    // B7: GEMM2 splitK2 (ZB, 64x64: 128 jobs) || dinvsum2
    gemm64_dev(B + O_X2, W2, ZB, KK1, 32, 64, sh, blockIdx.x, gridDim.x, 2);
    dinvsum_dev(BM2, KK1, NWB2, NSW2, DV2, SUM2);
    gsync();

    // B8: spmm2(ZB) -> X3 + score2 ; zero RANK ; zero ZA (GEMM3)
    spmm_dev<2>(BM2, SUM2, NWB2, NSW2, ZB, DV2, b2, B + O_X3, KK1, p2, SS, KEY);
    for (int i = gt; i < KK1; i += NT) RANK[i] = 0;
    zerof(ZA, KK2 * 128);
    gsync();

    // B9: rank pool2 (128 tiles)
    rank_dev(KEY, KK1, 64, RANK, (u64*)sh);
    gsync();

    // B10: gather2 -> X4 ; bmfilter BM2->BM4 ; zero BM6
    gather_dev(B + O_X3, SS, RANK, KK1, KK2, 64, B + O_X4, POS4);
    bmfilter_dev(BM2, SUM2, NWB2, NSW2, KK1, RANK, KK2, NWB4, BM4);
    for (int i = gt; i < KK3 * NWB6; i += NT) BM6[i] = 0;
    gsync();

    // B11: GEMM3 splitK4 (ZA) || dinvsum4
    gemm_dev(B + O_X4, nullptr, nullptr, 0, 0, W3, ZA, KK2, 64, 128, sh,
             blockIdx.x, gridDim.x, 4);
    dinvsum_dev(BM4, KK2, NWB4, NSW4, DV4, SUM4);
    gsync();

    // B12: spmm3(ZA) -> X5 + score3 ; zero RANK ; zero ZB (GEMM4)
    spmm_dev<4>(BM4, SUM4, NWB4, NSW4, ZA, DV4, b3, B + O_X5, KK2, p3, SS, KEY);
    for (int i = gt; i < KK2; i += NT) RANK[i] = 0;
    zerof(ZB, KK3 * 256);
    gsync();

    // B13: rank pool3 (32 tiles)
    rank_dev(KEY, KK2, 64, RANK, (u64*)sh);
    gsync();

    // B14: gather3 -> X6 ; bmfilter BM4->BM6
    gather_dev(B + O_X5, SS, RANK, KK2, KK3, 128, B + O_X6, POS6);
    bmfilter_dev(BM4, SUM4, NWB4, NSW4, KK2, RANK, KK3, NWB6, BM6);
    gsync();

    // B15: GEMM4 splitK4 (ZB) || dinvsum6
    gemm_dev(B + O_X6, nullptr, nullptr, 0, 0, W4, ZB, KK3, 128, 256, sh,
             blockIdx.x, gridDim.x, 4);
    dinvsum_dev(BM6, KK3, NWB6, NSW6, DV6, SUM6);
    gsync();

    // B16: spmm4(ZB) -> X7 ; zero ZA (GEMM5)
    spmm_dev<8>(BM6, SUM6, NWB6, NSW6, ZB, DV6, b4, B + O_X7, KK3,
                nullptr, nullptr, nullptr);
    zerof(ZA, KK2 * 128);
    gsync();

    // B17: GEMM5 splitK4 (ZA) fused concat(X7 via POS6, skip X5)
    gemm_dev(B + O_X7, POS6, B + O_X5, 256, 128, W5, ZA, KK2, 384, 128, sh,
             blockIdx.x, gridDim.x, 4);
    gsync();

    // B18: spmm5(ZA) -> X9 ; zero ZB (GEMM6)
    spmm_dev<4>(BM4, SUM4, NWB4, NSW4, ZA, DV4, b5, B + O_X9, KK2,
                nullptr, nullptr, nullptr);
    zerof(ZB, KK1 * 64);
    gsync();

    // B19: GEMM6 splitK4 (ZB) fused concat(X9 via POS4, skip X3)
    gemm_dev(B + O_X9, POS4, B + O_X3, 128, 64, W6, ZB, KK1, 192, 64, sh,
             blockIdx.x, gridDim.x, 4);
    gsync();

    // B20: spmm6(ZB) -> X11 ; zero ZA (GEMM7)
    spmm_dev<2>(BM2, SUM2, NWB2, NSW2, ZB, DV2, b6, B + O_X11, KK1,
                nullptr, nullptr, nullptr);
    zerof(ZA, NN * 32);
    gsync();

    // B21: GEMM7 splitK2 (ZA, M=32 path) fused concat(X11 via POS0, skip X1)
    gemm32_dev(B + O_X11, POS0, B + O_X1, 64, 32, W7, ZA, NN, 96, sh,
               blockIdx.x, gridDim.x, 2);
    gsync();

    // B22: final csragg(ZA) with fused readout
    csragg_dev(ZA, RP, COL, DV0, b7, nullptr, nullptr, nullptr, nullptr,
               batch, GSUM, GMAX, CNT);
    gsync();

    // ---- head ----
    if (blockIdx.x < NG) {
        int g = blockIdx.x;
        float* h  = sh;
        float* h2 = sh + 64;
        float* lg = sh + 128;
        if (tid < 64)
            h[tid] = eluf(tid < 32 ? unford(GMAX[g * 32 + tid])
                                   : GSUM[g * 32 + (tid - 32)] / CNT[g]);
        __syncthreads();
        if (tid < 64) {
            float acc = 0.f;
#pragma unroll
            for (int k = 0; k < 64; k++) acc += h[k] * Wl1[k * 64 + tid];
            h2[tid] = eluf(acc);
        }
        __syncthreads();
        if (tid < 10) {
            float a = bc[tid];
#pragma unroll
            for (int k = 0; k < 64; k++) a += h2[k] * Wc[k * 10 + tid];
            lg[tid] = a;
        }
        __syncthreads();
        if (tid == 0) {
            float m = lg[0];
            for (int c = 1; c < 10; c++) m = fmaxf(m, lg[c]);
            float se = 0.f;
            for (int c = 0; c < 10; c++) se += expf(lg[c] - m);
            sh[140] = m + logf(se);
        }
        __syncthreads();
        if (tid < 10) out[g * 10 + tid] = lg[tid] - sh[140];
    }
}

// ------------------------------- launcher ------------------------------------
extern "C" void kernel_launch(void* const* d_in, const int* in_sizes, int n_in,
                              void* d_out, int out_size) {
    (void)in_sizes; (void)n_in; (void)out_size;
    const float* x    = (const float*)d_in[0];
    const int*   ei   = (const int*)d_in[1];
    const int*   batch= (const int*)d_in[2];
    const float* W1 = (const float*)d_in[3],  *b1 = (const float*)d_in[4];
    const float* W2 = (const float*)d_in[5],  *b2 = (const float*)d_in[6];
    const float* W3 = (const float*)d_in[7],  *b3 = (const float*)d_in[8];
    const float* W4 = (const float*)d_in[9],  *b4 = (const float*)d_in[10];
    const float* W5 = (const float*)d_in[11], *b5 = (const float*)d_in[12];
    const float* W6 = (const float*)d_in[13], *b6 = (const float*)d_in[14];
    const float* W7 = (const float*)d_in[15], *b7 = (const float*)d_in[16];
    const float* p1 = (const float*)d_in[17];
    const float* p2 = (const float*)d_in[18];
    const float* p3 = (const float*)d_in[19];
    const float* Wl1= (const float*)d_in[20];
    const float* Wc = (const float*)d_in[21];
    const float* bc = (const float*)d_in[22];
    float* out = (float*)d_out;

    int dev = 0;
    cudaGetDevice(&dev);
    int nsm = 148;
    cudaDeviceGetAttribute(&nsm, cudaDevAttrMultiProcessorCount, dev);

    uk<<<nsm, 1024>>>(x, ei, batch, W1, b1, W2, b2, W3, b3, W4, b4,
                      W5, b5, W6, b6, W7, b7, p1, p2, p3, Wl1, Wc, bc, out);
}

// round 15
// speedup vs baseline: 1.2257x; 1.0093x over previous
#include <cuda_runtime.h>
#include <math.h>

#define NN 8192
#define EE 262144
#define KK1 4096
#define KK2 2048
#define KK3 1024
#define NG 64

typedef unsigned int u32;
typedef unsigned long long u64;

constexpr int NWB2 = KK1 / 32;
constexpr int NWB4 = KK2 / 32;
constexpr int NWB6 = KK3 / 32;
constexpr int NSW2 = NWB2 / 32;
constexpr int NSW4 = NWB4 / 32;
constexpr int NSW6 = NWB6 / 32;

// ------------------------- workspace layout (float units) --------------------
constexpr size_t O_X1   = 0;                 constexpr size_t S_X1   = (size_t)NN*32;
constexpr size_t O_X2   = O_X1+S_X1;         constexpr size_t S_X2   = (size_t)KK1*32;
constexpr size_t O_X3   = O_X2+S_X2;         constexpr size_t S_X3   = (size_t)KK1*64;
constexpr size_t O_X4   = O_X3+S_X3;         constexpr size_t S_X4   = (size_t)KK2*64;
constexpr size_t O_X5   = O_X4+S_X4;         constexpr size_t S_X5   = (size_t)KK2*128;
constexpr size_t O_X6   = O_X5+S_X5;         constexpr size_t S_X6   = (size_t)KK3*128;
constexpr size_t O_X7   = O_X6+S_X6;         constexpr size_t S_X7   = (size_t)KK3*256;
constexpr size_t O_X9   = O_X7+S_X7;         constexpr size_t S_X9   = (size_t)KK2*128;
constexpr size_t O_X11  = O_X9+S_X9;         constexpr size_t S_X11  = (size_t)KK1*64;
constexpr size_t O_ZA   = O_X11+S_X11;       constexpr size_t S_ZA   = 262144;
constexpr size_t O_ZB   = O_ZA+S_ZA;         constexpr size_t S_ZB   = 262144;
constexpr size_t O_COL  = O_ZB+S_ZB;         constexpr size_t S_COL  = EE;
constexpr size_t O_DEG0 = O_COL+S_COL;       constexpr size_t S_DEG0 = NN;
constexpr size_t O_DINV0= O_DEG0+S_DEG0;     constexpr size_t S_DINV0= NN;
constexpr size_t O_DINV2= O_DINV0+S_DINV0;   constexpr size_t S_DINV2= KK1;
constexpr size_t O_DINV4= O_DINV2+S_DINV2;   constexpr size_t S_DINV4= KK2;
constexpr size_t O_DINV6= O_DINV4+S_DINV4;   constexpr size_t S_DINV6= KK3;
constexpr size_t O_S    = O_DINV6+S_DINV6;   constexpr size_t S_S    = NN;
constexpr size_t O_KEY  = O_S+S_S;           constexpr size_t S_KEY  = (size_t)NN*2;
constexpr size_t O_RANK = O_KEY+S_KEY;       constexpr size_t S_RANK = NN;
constexpr size_t O_POS0 = O_RANK+S_RANK;     constexpr size_t S_POS0 = NN;
constexpr size_t O_POS4 = O_POS0+S_POS0;     constexpr size_t S_POS4 = KK1;
constexpr size_t O_POS6 = O_POS4+S_POS4;     constexpr size_t S_POS6 = KK2;
constexpr size_t O_RP   = O_POS6+S_POS6;     constexpr size_t S_RP   = NN+8;
constexpr size_t O_OFF  = O_RP+S_RP;         constexpr size_t S_OFF  = NN;
constexpr size_t O_BM2  = O_OFF+S_OFF;       constexpr size_t S_BM2  = (size_t)KK1*NWB2;
constexpr size_t O_BM4  = O_BM2+S_BM2;       constexpr size_t S_BM4  = (size_t)KK2*NWB4;
constexpr size_t O_BM6  = O_BM4+S_BM4;       constexpr size_t S_BM6  = (size_t)KK3*NWB6;
constexpr size_t O_SUM2 = O_BM6+S_BM6;       constexpr size_t S_SUM2 = (size_t)KK1*NSW2;
constexpr size_t O_SUM4 = O_SUM2+S_SUM2;     constexpr size_t S_SUM4 = (size_t)KK2*NSW4;
constexpr size_t O_SUM6 = O_SUM4+S_SUM4;     constexpr size_t S_SUM6 = (size_t)KK3*NSW6;
constexpr size_t O_GSUM = O_SUM6+S_SUM6;     constexpr size_t S_GSUM = (size_t)NG*32;
constexpr size_t O_GMAX = O_GSUM+S_GSUM;     constexpr size_t S_GMAX = (size_t)NG*32;
constexpr size_t O_CNT  = O_GMAX+S_GMAX;     constexpr size_t S_CNT  = NG;
constexpr size_t WS_TOTAL = O_CNT + S_CNT;

__device__ __align__(256) float g_ws[WS_TOTAL];
__device__ unsigned g_arrive = 0;

// ------------------------------- helpers -------------------------------------
__device__ __forceinline__ float eluf(float x) { return x > 0.f ? x : expm1f(x); }
__device__ __forceinline__ unsigned ford(float f) {
    unsigned u = __float_as_uint(f);
    return (u & 0x80000000u) ? ~u : (u | 0x80000000u);
}
__device__ __forceinline__ float unford(unsigned u) {
    return __uint_as_float((u & 0x80000000u) ? (u & 0x7fffffffu) : ~u);
}

// chip-wide barrier: release-arrive / acquire-spin (1 block/SM)
__device__ __forceinline__ void gsync() {
    __syncthreads();
    if (threadIdx.x == 0) {
        unsigned t;
        asm volatile("atom.release.gpu.add.u32 %0, [%1], 1;"
                     : "=r"(t) : "l"(&g_arrive) : "memory");
        unsigned target = (t / gridDim.x + 1u) * gridDim.x;
        unsigned v;
        do {
            asm volatile("ld.acquire.gpu.u32 %0, [%1];"
                         : "=r"(v) : "l"(&g_arrive) : "memory");
        } while (v < target);
    }
    __syncthreads();
}

__device__ __forceinline__ void zerof(float* p, int n) {
    int gt = blockIdx.x * blockDim.x + threadIdx.x, NT = gridDim.x * blockDim.x;
    for (int i = gt; i < n; i += NT) p[i] = 0.f;
}

// ---------------------------- phase device funcs ------------------------------

__device__ __forceinline__ float a_elem(const float* __restrict__ X,
                                        const int* __restrict__ pos,
                                        const float* __restrict__ skip,
                                        int F1, int F2, int K, int gi, int kk) {
    if (!pos) return X[(size_t)gi * K + kk];
    if (kk < F1) {
        int p = pos[gi];
        return (p >= 0) ? eluf(X[(size_t)p * F1 + kk]) : 0.f;
    }
    return eluf(skip[(size_t)gi * F2 + (kk - F1)]);
}

// 128x64-tile GEMM, 1024 threads, 4x2 micro; KS-deep slabs, double-buffered
// smem (1 sync/slab); split-K atomicAdd accumulate. KS must divide K/SK.
template<int KS>
__device__ void gemm_dev(const float* __restrict__ X, const int* __restrict__ pos,
                         const float* __restrict__ skip, int F1, int F2,
                         const float* __restrict__ W, float* __restrict__ out,
                         int n, int K, int M, float* sh, int bstart, int bstride,
                         int SK) {
    constexpr int ABUF = KS * 132;
    constexpr int GB   = ABUF + KS * 66;
    constexpr int NA   = (128 * KS) / 1024;   // A elems per thread
    constexpr int NBW  = (64 * KS) / 1024;    // B elems per thread (>=1)
    int tid = threadIdx.x;
    int tm = (tid >> 5) << 2;
    int tn = (tid & 31) << 1;
    int am = tid / KS, ak = tid % KS;         // A loader base (power-of-2 KS)
    int ntn = (M + 63) >> 6;
    int ntm = n >> 7;
    int ntile = ntm * ntn;
    int njobs = ntile * SK;
    int Kb = K / SK;
    for (int j = bstart; j < njobs; j += bstride) {
        int t = j % ntile, kh = j / ntile;
        int kbeg = kh * Kb, kend = kbeg + Kb;
        int bm = (t / ntn) << 7, bn = (t % ntn) << 6;
        float acc[4][2];
#pragma unroll
        for (int r = 0; r < 4; r++) { acc[r][0] = 0.f; acc[r][1] = 0.f; }
        float ra[NA], rb[NBW];
#pragma unroll
        for (int i = 0; i < NA; i++)
            ra[i] = a_elem(X, pos, skip, F1, F2, K, bm + am + i * (1024 / KS), kbeg + ak);
#pragma unroll
        for (int i = 0; i < NBW; i++) {
            int l = tid + i * 1024, bk = l >> 6, bj = l & 63;
            rb[i] = (bn + bj < M) ? W[(size_t)(kbeg + bk) * M + (bn + bj)] : 0.f;
        }
        int cur = 0;
        __syncthreads();   // all readers of previous job's smem are done
        for (int kk = kbeg; kk < kend; kk += KS) {
            float* As = sh + cur * GB;
            float* Bs = As + ABUF;
#pragma unroll
            for (int i = 0; i < NA; i++)
                As[ak * 132 + am + i * (1024 / KS)] = ra[i];
#pragma unroll
            for (int i = 0; i < NBW; i++) {
                int l = tid + i * 1024;
                Bs[(l >> 6) * 66 + (l & 63)] = rb[i];
            }
            __syncthreads();
            if (kk + KS < kend) {
#pragma unroll
                for (int i = 0; i < NA; i++)
                    ra[i] = a_elem(X, pos, skip, F1, F2, K,
                                   bm + am + i * (1024 / KS), kk + KS + ak);
#pragma unroll
                for (int i = 0; i < NBW; i++) {
                    int l = tid + i * 1024, bk = l >> 6, bj = l & 63;
                    rb[i] = (bn + bj < M) ? W[(size_t)(kk + KS + bk) * M + (bn + bj)] : 0.f;
                }
            }
#pragma unroll
            for (int k = 0; k < KS; k++) {
                float4 aa = *(const float4*)&As[k * 132 + tm];
                float2 bb = *(const float2*)&Bs[k * 66 + tn];
                acc[0][0] += aa.x * bb.x; acc[0][1] += aa.x * bb.y;
                acc[1][0] += aa.y * bb.x; acc[1][1] += aa.y * bb.y;
                acc[2][0] += aa.z * bb.x; acc[2][1] += aa.z * bb.y;
                acc[3][0] += aa.w * bb.x; acc[3][1] += aa.w * bb.y;
            }
            cur ^= 1;
        }
        int gi = bm + tm, gj = bn + tn;
        if (gj < M) {
#pragma unroll
            for (int r = 0; r < 4; r++)
                atomicAdd(&out[(size_t)(gi + r) * M + gj], acc[r][0]);
            if (gj + 1 < M) {
#pragma unroll
                for (int r = 0; r < 4; r++)
                    atomicAdd(&out[(size_t)(gi + r) * M + gj + 1], acc[r][1]);
            }
        }
    }
}

// 128x32-tile GEMM for M==32, 1024 threads, 4x1 micro; KS-deep slabs,
// double-buffered smem.
template<int KS>
__device__ void gemm32_dev(const float* __restrict__ X, const int* __restrict__ pos,
                           const float* __restrict__ skip, int F1, int F2,
                           const float* __restrict__ W, float* __restrict__ out,
                           int n, int K, float* sh, int bstart, int bstride,
                           int SK) {
    constexpr int ABUF = KS * 132;
    constexpr int GB   = ABUF + KS * 33;
    constexpr int NA   = (128 * KS) / 1024;
    int tid = threadIdx.x;
    int tm = (tid >> 5) << 2;
    int tn = tid & 31;
    int am = tid / KS, ak = tid % KS;
    int bactive = (tid < KS * 32);
    int bk = tid >> 5, bj = tid & 31;
    int ntm = n >> 7;
    int njobs = ntm * SK;
    int Kb = K / SK;
    for (int j = bstart; j < njobs; j += bstride) {
        int t = j % ntm, kh = j / ntm;
        int kbeg = kh * Kb, kend = kbeg + Kb;
        int bm = t << 7;
        float a0 = 0.f, a1 = 0.f, a2 = 0.f, a3 = 0.f;
        float ra[NA];
#pragma unroll
        for (int i = 0; i < NA; i++)
            ra[i] = a_elem(X, pos, skip, F1, F2, K, bm + am + i * (1024 / KS), kbeg + ak);
        float rb = bactive ? W[(size_t)(kbeg + bk) * 32 + bj] : 0.f;
        int cur = 0;
        __syncthreads();
        for (int kk = kbeg; kk < kend; kk += KS) {
            float* As = sh + cur * GB;
            float* Bs = As + ABUF;
#pragma unroll
            for (int i = 0; i < NA; i++)
                As[ak * 132 + am + i * (1024 / KS)] = ra[i];
            if (bactive) Bs[bk * 33 + bj] = rb;
            __syncthreads();
            if (kk + KS < kend) {
#pragma unroll
                for (int i = 0; i < NA; i++)
                    ra[i] = a_elem(X, pos, skip, F1, F2, K,
                                   bm + am + i * (1024 / KS), kk + KS + ak);
                rb = bactive ? W[(size_t)(kk + KS + bk) * 32 + bj] : 0.f;
            }
#pragma unroll
            for (int k = 0; k < KS; k++) {
                float4 aa = *(const float4*)&As[k * 132 + tm];
                float b  = Bs[k * 33 + tn];
                a0 += aa.x * b; a1 += aa.y * b;
                a2 += aa.z * b; a3 += aa.w * b;
            }
            cur ^= 1;
        }
        int gi = bm + tm;
        atomicAdd(&out[(size_t)gi * 32 + tn], a0);
        atomicAdd(&out[(size_t)(gi + 1) * 32 + tn], a1);
        atomicAdd(&out[(size_t)(gi + 2) * 32 + tn], a2);
        atomicAdd(&out[(size_t)(gi + 3) * 32 + tn], a3);
    }
}

// 64x64-tile GEMM, 1024 threads, 2x2 micro; double-buffered smem.  [R14]
constexpr int GBUF64 = 16 * 66 + 16 * 66;
__device__ void gemm64_dev(const float* __restrict__ X,
                           const float* __restrict__ W, float* __restrict__ out,
                           int n, int K, int M, float* sh, int bstart, int bstride,
                           int SK) {
    int tid = threadIdx.x;
    int tm = (tid >> 5) << 1;
    int tn = (tid & 31) << 1;
    int lm = tid >> 4, lk = tid & 15;
    int bk = tid >> 6, bj = tid & 63;
    int ntn = (M + 63) >> 6;
    int ntm = n >> 6;
    int ntile = ntm * ntn;
    int njobs = ntile * SK;
    int Kb = K / SK;
    for (int j = bstart; j < njobs; j += bstride) {
        int t = j % ntile, kh = j / ntile;
        int kbeg = kh * Kb, kend = kbeg + Kb;
        int bm = (t / ntn) << 6, bn = (t % ntn) << 6;
        float a00 = 0.f, a01 = 0.f, a10 = 0.f, a11 = 0.f;
        float ra = X[(size_t)(bm + lm) * K + (kbeg + lk)];
        float rb = (bn + bj < M) ? W[(size_t)(kbeg + bk) * M + (bn + bj)] : 0.f;
        int cur = 0;
        __syncthreads();
        for (int kk = kbeg; kk < kend; kk += 16) {
            float* As = sh + cur * GBUF64;
            float* Bs = As + 16 * 66;
            As[lk * 66 + lm] = ra;
            Bs[bk * 66 + bj] = rb;
            __syncthreads();
            if (kk + 16 < kend) {
                ra = X[(size_t)(bm + lm) * K + (kk + 16 + lk)];
                rb = (bn + bj < M) ? W[(size_t)(kk + 16 + bk) * M + (bn + bj)] : 0.f;
            }
#pragma unroll
            for (int k = 0; k < 16; k++) {
                float2 aa = *(const float2*)&As[k * 66 + tm];
                float2 bb = *(const float2*)&Bs[k * 66 + tn];
                a00 += aa.x * bb.x; a01 += aa.x * bb.y;
                a10 += aa.y * bb.x; a11 += aa.y * bb.y;
            }
            cur ^= 1;
        }
        int gi = bm + tm, gj = bn + tn;
        if (gj < M) {
            atomicAdd(&out[(size_t)gi * M + gj], a00);
            atomicAdd(&out[(size_t)(gi + 1) * M + gj], a10);
            if (gj + 1 < M) {
                atomicAdd(&out[(size_t)gi * M + gj + 1], a01);
                atomicAdd(&out[(size_t)(gi + 1) * M + gj + 1], a11);
            }
        }
    }
}

// rank: 2048-row i-tiles, 2 rows per thread; CH-wide j-chunks in smem
__device__ void rank_dev(const u64* __restrict__ key, int n, int CH,
                         int* __restrict__ rank, u64* shk) {
    int nti = n >> 11;
    int ntj = n / CH;
    for (int t = blockIdx.x; t < nti * ntj; t += gridDim.x) {
        int ti = t / ntj, tj = t - ti * ntj;
        int i0 = (ti << 11) + threadIdx.x;
        int j0 = tj * CH;
        __syncthreads();
        for (int l = threadIdx.x; l < CH; l += 1024) shk[l] = key[j0 + l];
        __syncthreads();
        u64 ka = key[i0], kb = key[i0 + 1024];
        int ca = 0, cb = 0;
#pragma unroll 8
        for (int j = 0; j < CH; j++) {
            u64 kj = shk[j];
            ca += (kj > ka) ? 1 : 0;
            cb += (kj > kb) ? 1 : 0;
        }
        if (ca) atomicAdd(&rank[i0], ca);
        if (cb) atomicAdd(&rank[i0 + 1024], cb);
    }
}

__device__ void gather_dev(const float* __restrict__ x, const float* __restrict__ s,
                           const int* __restrict__ rank, int n, int k, int F,
                           float* __restrict__ out, int* __restrict__ pos) {
    int gt = blockIdx.x * blockDim.x + threadIdx.x, NT = gridDim.x * blockDim.x;
    for (int t = gt; t < n * F; t += NT) {
        int i = t / F, f = t - i * F;
        int r = rank[i];
        if (f == 0) pos[i] = (r < k) ? r : -1;
        if (r < k) {
            float gate = 1.f / (1.f + expf(-s[i]));
            out[(size_t)r * F + f] = eluf(x[t] * gate);
        }
    }
}

__device__ void bmfilter_dev(const u32* __restrict__ bms, const u32* __restrict__ ssum,
                             int nws, int nssw, int nsrc, const int* __restrict__ rank,
                             int k, int nwd, u32* __restrict__ bmd) {
    int lane = threadIdx.x & 31;
    int wg = (blockIdx.x * blockDim.x + threadIdx.x) >> 5;
    int NWp = (gridDim.x * blockDim.x) >> 5;
    for (int i = wg; i < nsrc; i += NWp) {
        int b = rank[i];
        if (b >= k) continue;
        const u32* row = bms + (size_t)i * nws;
        const u32* srow = ssum + (size_t)i * nssw;
        for (int w = lane; w < nws; w += 32) {
            if (!((srow[w >> 5] >> (w & 31)) & 1u)) continue;
            u32 word = row[w];
            while (word) {
                int bit = __ffs(word) - 1; word &= word - 1;
                int ps = rank[(w << 5) + bit];
                if (ps < k) atomicOr(&bmd[(size_t)b * nwd + (ps >> 5)], 1u << (ps & 31));
            }
        }
    }
}

__device__ void dinvsum_dev(const u32* __restrict__ bm, int n, int nw, int nsw,
                            float* __restrict__ dv, u32* __restrict__ sum) {
    int lane = threadIdx.x & 31;
    int wg = (blockIdx.x * blockDim.x + threadIdx.x) >> 5;
    int NWp = (gridDim.x * blockDim.x) >> 5;
    for (int r = wg; r < n; r += NWp) {
        int c = 0;
        for (int g = 0; g < nsw; g++) {
            u32 word = bm[(size_t)r * nw + (g << 5) + lane];
            u32 m = __ballot_sync(0xffffffffu, word != 0u);
            c += __popc(word);
            if (lane == 0) sum[(size_t)r * nsw + g] = m;
        }
#pragma unroll
        for (int o = 16; o > 0; o >>= 1) c += __shfl_xor_sync(0xffffffffu, c, o);
        if (lane == 0) dv[r] = rsqrtf((float)(c + 1));
    }
}

// bitmap SpMM; neighbors batch-decoded (NB at a time) for MLP.
template<int FW>
__device__ void spmm_dev(const u32* __restrict__ bm, const u32* __restrict__ sum,
                         int nw, int nsw, const float* __restrict__ z,
                         const float* __restrict__ dv, const float* __restrict__ bias,
                         float* __restrict__ out, int n,
                         const float* __restrict__ p, float* __restrict__ ss,
                         u64* __restrict__ key) {
    const int F = FW * 32;
    const int NB = (FW <= 4) ? 4 : 2;
    int lane = threadIdx.x & 31;
    int wg = (blockIdx.x * blockDim.x + threadIdx.x) >> 5;
    int NWp = (gridDim.x * blockDim.x) >> 5;
    float bl[FW], pl[FW];
#pragma unroll
    for (int c = 0; c < FW; c++) bl[c] = bias[lane + 32 * c];
    float invn = 0.f;
    if (p) {
        float q = 0.f;
#pragma unroll
        for (int c = 0; c < FW; c++) { pl[c] = p[lane + 32 * c]; q += pl[c] * pl[c]; }
#pragma unroll
        for (int o = 16; o > 0; o >>= 1) q += __shfl_xor_sync(0xffffffffu, q, o);
        invn = rsqrtf(q);
    }
    for (int r = wg; r < n; r += NWp) {
        float dr = dv[r];
        float acc[FW];
#pragma unroll
        for (int c = 0; c < FW; c++) acc[c] = dr * z[(size_t)r * F + lane + 32 * c];
        const u32* row = bm + (size_t)r * nw;
        const u32* srow = sum + (size_t)r * nsw;
        int nbuf[NB];
        int m = 0;
        auto flush = [&](int mc) {
            float dvs[NB];
            float tmp[NB][FW];
#pragma unroll
            for (int i = 0; i < NB; i++) if (i < mc) dvs[i] = dv[nbuf[i]];
#pragma unroll
            for (int i = 0; i < NB; i++) if (i < mc) {
                const float* zs = z + (size_t)nbuf[i] * F + lane;
#pragma unroll
                for (int c = 0; c < FW; c++) tmp[i][c] = zs[32 * c];
            }
#pragma unroll
            for (int i = 0; i < NB; i++) if (i < mc)
#pragma unroll
                for (int c = 0; c < FW; c++) acc[c] += dvs[i] * tmp[i][c];
        };
        for (int sw = 0; sw < nsw; sw++) {
            u32 sword = srow[sw];
            while (sword) {
                int wb = __ffs(sword) - 1; sword &= sword - 1;
                int w = (sw << 5) + wb;
                u32 word = row[w];
                while (word) {
                    int b = __ffs(word) - 1; word &= word - 1;
                    nbuf[m++] = (w << 5) + b;
                    if (m == NB) { flush(NB); m = 0; }
                }
            }
        }
        if (m) flush(m);
        float sc = 0.f;
#pragma unroll
        for (int c = 0; c < FW; c++) {
            float v = eluf(dr * acc[c] + bl[c]);
            out[(size_t)r * F + lane + 32 * c] = v;
            if (p) sc += v * pl[c];
        }
        if (p) {
#pragma unroll
            for (int o = 16; o > 0; o >>= 1) sc += __shfl_xor_sync(0xffffffffu, sc, o);
            if (lane == 0) {
                float sv = sc * invn;
                ss[r] = sv;
                key[r] = ((u64)ford(sv) << 32) | (u32)(~r);
            }
        }
    }
}

__device__ void csragg_dev(const float* __restrict__ z, const int* __restrict__ rp,
                           const int* __restrict__ col, const float* __restrict__ dv,
                           const float* __restrict__ bias, float* __restrict__ out,
                           const float* __restrict__ p, float* __restrict__ ss,
                           u64* __restrict__ key,
                           const int* __restrict__ batch, float* __restrict__ gsum,
                           u32* __restrict__ gmax, float* __restrict__ cnt) {
    int lane = threadIdx.x & 31;
    int wg = (blockIdx.x * blockDim.x + threadIdx.x) >> 5;
    int NWp = (gridDim.x * blockDim.x) >> 5;
    float invn = 0.f, pv = 0.f;
    if (p) {
        pv = p[lane];
        float q = pv * pv;
#pragma unroll
        for (int o = 16; o > 0; o >>= 1) q += __shfl_xor_sync(0xffffffffu, q, o);
        invn = rsqrtf(q);
    }
    float bl = bias[lane];
    for (int r = wg; r < NN; r += NWp) {
        float dr = dv[r];
        float acc = dr * z[r * 32 + lane];
        int e = rp[r], e1 = rp[r + 1];
        for (; e + 7 < e1; e += 8) {
            int s[8]; float d[8], v[8];
#pragma unroll
            for (int i = 0; i < 8; i++) s[i] = col[e + i];
#pragma unroll
            for (int i = 0; i < 8; i++) { d[i] = dv[s[i]]; v[i] = z[s[i] * 32 + lane]; }
#pragma unroll
            for (int i = 0; i < 8; i++) acc += d[i] * v[i];
        }
        for (; e < e1; e++) { int s = col[e]; acc += dv[s] * z[s * 32 + lane]; }
        float val = eluf(dr * acc + bl);
        if (out) {
            out[r * 32 + lane] = val;
            if (p) {
                float sc = val * pv;
#pragma unroll
                for (int o = 16; o > 0; o >>= 1) sc += __shfl_xor_sync(0xffffffffu, sc, o);
                if (lane == 0) {
                    float sv = sc * invn;
                    ss[r] = sv;
                    key[r] = ((u64)ford(sv) << 32) | (u32)(~r);
                }
            }
        } else {
            int g = batch[r];
            atomicAdd(&gsum[g * 32 + lane], val);
            atomicMax(&gmax[g * 32 + lane], ford(val));
            if (lane == 0) atomicAdd(&cnt[g], 1.f);
        }
    }
}

// --------------------------------- megakernel --------------------------------
__global__ void __launch_bounds__(1024, 1)
uk(const float* __restrict__ x, const int* __restrict__ ei, const int* __restrict__ batch,
   const float* W1, const float* b1, const float* W2, const float* b2,
   const float* W3, const float* b3, const float* W4, const float* b4,
   const float* W5, const float* b5, const float* W6, const float* b6,
   const float* W7, const float* b7, const float* p1, const float* p2, const float* p3,
   const float* Wl1, const float* Wc, const float* bc, float* __restrict__ out) {
    __shared__ float sh[12800];   // 2x6336 KS=32 GEMM double-buffer; other phases reuse
    float* B = g_ws;
    float* ZA  = B + O_ZA;
    float* ZB  = B + O_ZB;
    int*  COL  = (int*)(B + O_COL);
    int*  DEG0 = (int*)(B + O_DEG0);
    float* DV0 = B + O_DINV0;
    float* DV2 = B + O_DINV2;
    float* DV4 = B + O_DINV4;
    float* DV6 = B + O_DINV6;
    float* SS  = B + O_S;
    u64*  KEY  = (u64*)(B + O_KEY);
    int*  RANK = (int*)(B + O_RANK);
    int*  POS0 = (int*)(B + O_POS0);
    int*  POS4 = (int*)(B + O_POS4);
    int*  POS6 = (int*)(B + O_POS6);
    int*  RP   = (int*)(B + O_RP);
    int*  OFF  = (int*)(B + O_OFF);
    u32*  BM2  = (u32*)(B + O_BM2);
    u32*  BM4  = (u32*)(B + O_BM4);
    u32*  BM6  = (u32*)(B + O_BM6);
    u32*  SUM2 = (u32*)(B + O_SUM2);
    u32*  SUM4 = (u32*)(B + O_SUM4);
    u32*  SUM6 = (u32*)(B + O_SUM6);
    float* GSUM= B + O_GSUM;
    u32*  GMAX = (u32*)(B + O_GMAX);
    float* CNT = B + O_CNT;

    int tid = threadIdx.x;
    int gt  = blockIdx.x * 1024 + tid;
    int NT  = gridDim.x * 1024;

    // B1: degree histogram (DEG0 zero by contract) ; prologue zeroing
    for (int e = gt; e < EE; e += NT) atomicAdd(&DEG0[ei[EE + e]], 1);
    for (int i = gt; i < KK1 * NWB2; i += NT) BM2[i] = 0;
    for (int i = gt; i < NG * 32; i += NT) { GSUM[i] = 0.f; GMAX[i] = 0u; }
    for (int i = gt; i < NG; i += NT) CNT[i] = 0.f;
    zerof(ZA, NN * 32);
    zerof(ZB, KK1 * 64);
    gsync();

    // B2: block 0 CSR scan || GEMM1 splitK2 (ZA, M=32 path, KS=32)
    if (blockIdx.x == 0) {
        int base = tid * 8;
        int s = 0;
#pragma unroll
        for (int j = 0; j < 8; j++) s += DEG0[base + j];
        int* shi = (int*)sh;
        shi[tid] = s;
        __syncthreads();
        for (int o = 1; o < 1024; o <<= 1) {
            int v = (tid >= o) ? shi[tid - o] : 0;
            __syncthreads();
            shi[tid] += v;
            __syncthreads();
        }
        int run = shi[tid] - s;
#pragma unroll
        for (int j = 0; j < 8; j++) {
            int d = DEG0[base + j];
            RP[base + j] = run;
            OFF[base + j] = run;
            DV0[base + j] = rsqrtf((float)(d + 1));
            run += d;
        }
        if (tid == 1023) RP[NN] = run;
    } else {
        gemm32_dev<32>(x, nullptr, nullptr, 0, 0, W1, ZA, NN, 128, sh,
                       blockIdx.x - 1, gridDim.x - 1, 2);
    }
    gsync();

    // B3: CSR scatter ; re-zero DEG0
    for (int e = gt; e < EE; e += NT) {
        int s = ei[e], d = ei[EE + e];
        int pp = atomicAdd(&OFF[d], 1);
        COL[pp] = s;
    }
    for (int i = gt; i < NN; i += NT) DEG0[i] = 0;
    gsync();

    // B4: X1 = csragg(ZA) + score1/key ; zero RANK
    csragg_dev(ZA, RP, COL, DV0, b1, B + O_X1, p1, SS, KEY,
               nullptr, nullptr, nullptr, nullptr);
    for (int i = gt; i < NN; i += NT) RANK[i] = 0;
    gsync();

    // B5: rank pool1 (128 tiles)
    rank_dev(KEY, NN, 256, RANK, (u64*)sh);
    gsync();

    // B6: gather1 -> X2 ; bm_edges -> BM2 ; zero BM4
    gather_dev(B + O_X1, SS, RANK, NN, KK1, 32, B + O_X2, POS0);
    for (int e = gt; e < EE; e += NT) {
        int rs = RANK[ei[e]], rd = RANK[ei[EE + e]];
        if (rs < KK1 && rd < KK1)
            atomicOr(&BM2[(size_t)rd * NWB2 + (rs >> 5)], 1u << (rs & 31));
    }
    for (int i = gt; i < KK2 * NWB4; i += NT) BM4[i] = 0;
    gsync();

    // B7: GEMM2 splitK2 (ZB, 64x64: 128 jobs) || dinvsum2
    gemm64_dev(B + O_X2, W2, ZB, KK1, 32, 64, sh, blockIdx.x, gridDim.x, 2);
    dinvsum_dev(BM2, KK1, NWB2, NSW2, DV2, SUM2);
    gsync();

    // B8: spmm2(ZB) -> X3 + score2 ; zero RANK ; zero ZA (GEMM3)
    spmm_dev<2>(BM2, SUM2, NWB2, NSW2, ZB, DV2, b2, B + O_X3, KK1, p2, SS, KEY);
    for (int i = gt; i < KK1; i += NT) RANK[i] = 0;
    zerof(ZA, KK2 * 128);
    gsync();

    // B9: rank pool2 (128 tiles)
    rank_dev(KEY, KK1, 64, RANK, (u64*)sh);
    gsync();

    // B10: gather2 -> X4 ; bmfilter BM2->BM4 ; zero BM6
    gather_dev(B + O_X3, SS, RANK, KK1, KK2, 64, B + O_X4, POS4);
    bmfilter_dev(BM2, SUM2, NWB2, NSW2, KK1, RANK, KK2, NWB4, BM4);
    for (int i = gt; i < KK3 * NWB6; i += NT) BM6[i] = 0;
    gsync();

    // B11: GEMM3 splitK4 (ZA, KS=16: Kb=16) || dinvsum4
    gemm_dev<16>(B + O_X4, nullptr, nullptr, 0, 0, W3, ZA, KK2, 64, 128, sh,
                 blockIdx.x, gridDim.x, 4);
    dinvsum_dev(BM4, KK2, NWB4, NSW4, DV4, SUM4);
    gsync();

    // B12: spmm3(ZA) -> X5 + score3 ; zero RANK ; zero ZB (GEMM4)
    spmm_dev<4>(BM4, SUM4, NWB4, NSW4, ZA, DV4, b3, B + O_X5, KK2, p3, SS, KEY);
    for (int i = gt; i < KK2; i += NT) RANK[i] = 0;
    zerof(ZB, KK3 * 256);
    gsync();

    // B13: rank pool3 (128 tiles, CH=16)
    rank_dev(KEY, KK2, 16, RANK, (u64*)sh);
    gsync();

    // B14: gather3 -> X6 ; bmfilter BM4->BM6
    gather_dev(B + O_X5, SS, RANK, KK2, KK3, 128, B + O_X6, POS6);
    bmfilter_dev(BM4, SUM4, NWB4, NSW4, KK2, RANK, KK3, NWB6, BM6);
    gsync();

    // B15: GEMM4 splitK4 (ZB, KS=32: Kb=32, 1 slab) || dinvsum6
    gemm_dev<32>(B + O_X6, nullptr, nullptr, 0, 0, W4, ZB, KK3, 128, 256, sh,
                 blockIdx.x, gridDim.x, 4);
    dinvsum_dev(BM6, KK3, NWB6, NSW6, DV6, SUM6);
    gsync();

    // B16: spmm4(ZB) -> X7 ; zero ZA (GEMM5)
    spmm_dev<8>(BM6, SUM6, NWB6, NSW6, ZB, DV6, b4, B + O_X7, KK3,
                nullptr, nullptr, nullptr);
    zerof(ZA, KK2 * 128);
    gsync();

    // B17: GEMM5 splitK4 (ZA, KS=32: Kb=96, 3 slabs) fused concat(X7/POS6, X5)
    gemm_dev<32>(B + O_X7, POS6, B + O_X5, 256, 128, W5, ZA, KK2, 384, 128, sh,
                 blockIdx.x, gridDim.x, 4);
    gsync();

    // B18: spmm5(ZA) -> X9 ; zero ZB (GEMM6)
    spmm_dev<4>(BM4, SUM4, NWB4, NSW4, ZA, DV4, b5, B + O_X9, KK2,
                nullptr, nullptr, nullptr);
    zerof(ZB, KK1 * 64);
    gsync();

    // B19: GEMM6 splitK4 (ZB, KS=16: Kb=48, 3 slabs) fused concat(X9/POS4, X3)
    gemm_dev<16>(B + O_X9, POS4, B + O_X3, 128, 64, W6, ZB, KK1, 192, 64, sh,
                 blockIdx.x, gridDim.x, 4);
    gsync();

    // B20: spmm6(ZB) -> X11 ; zero ZA (GEMM7)
    spmm_dev<2>(BM2, SUM2, NWB2, NSW2, ZB, DV2, b6, B + O_X11, KK1,
                nullptr, nullptr, nullptr);
    zerof(ZA, NN * 32);
    gsync();

    // B21: GEMM7 splitK2 (ZA, M=32 path, KS=16: Kb=48) fused concat(X11/POS0, X1)
    gemm32_dev<16>(B + O_X11, POS0, B + O_X1, 64, 32, W7, ZA, NN, 96, sh,
                   blockIdx.x, gridDim.x, 2);
    gsync();

    // B22: final csragg(ZA) with fused readout
    csragg_dev(ZA, RP, COL, DV0, b7, nullptr, nullptr, nullptr, nullptr,
               batch, GSUM, GMAX, CNT);
    gsync();

    // ---- head ----
    if (blockIdx.x < NG) {
        int g = blockIdx.x;
        float* h  = sh;
        float* h2 = sh + 64;
        float* lg = sh + 128;
        if (tid < 64)
            h[tid] = eluf(tid < 32 ? unford(GMAX[g * 32 + tid])
                                   : GSUM[g * 32 + (tid - 32)] / CNT[g]);
        __syncthreads();
        if (tid < 64) {
            float acc = 0.f;
#pragma unroll
            for (int k = 0; k < 64; k++) acc += h[k] * Wl1[k * 64 + tid];
            h2[tid] = eluf(acc);
        }
        __syncthreads();
        if (tid < 10) {
            float a = bc[tid];
#pragma unroll
            for (int k = 0; k < 64; k++) a += h2[k] * Wc[k * 10 + tid];
            lg[tid] = a;
        }
        __syncthreads();
        if (tid == 0) {
            float m = lg[0];
            for (int c = 1; c < 10; c++) m = fmaxf(m, lg[c]);
            float se = 0.f;
            for (int c = 0; c < 10; c++) se += expf(lg[c] - m);
            sh[140] = m + logf(se);
        }
        __syncthreads();
        if (tid < 10) out[g * 10 + tid] = lg[tid] - sh[140];
    }
}

// ------------------------------- launcher ------------------------------------
extern "C" void kernel_launch(void* const* d_in, const int* in_sizes, int n_in,
                              void* d_out, int out_size) {
    (void)in_sizes; (void)n_in; (void)out_size;
    const float* x    = (const float*)d_in[0];
    const int*   ei   = (const int*)d_in[1];
    const int*   batch= (const int*)d_in[2];
    const float* W1 = (const float*)d_in[3],  *b1 = (const float*)d_in[4];
    const float* W2 = (const float*)d_in[5],  *b2 = (const float*)d_in[6];
    const float* W3 = (const float*)d_in[7],  *b3 = (const float*)d_in[8];
    const float* W4 = (const float*)d_in[9],  *b4 = (const float*)d_in[10];
    const float* W5 = (const float*)d_in[11], *b5 = (const float*)d_in[12];
    const float* W6 = (const float*)d_in[13], *b6 = (const float*)d_in[14];
    const float* W7 = (const float*)d_in[15], *b7 = (const float*)d_in[16];
    const float* p1 = (const float*)d_in[17];
    const float* p2 = (const float*)d_in[18];
    const float* p3 = (const float*)d_in[19];
    const float* Wl1= (const float*)d_in[20];
    const float* Wc = (const float*)d_in[21];
    const float* bc = (const float*)d_in[22];
    float* out = (float*)d_out;

    int dev = 0;
    cudaGetDevice(&dev);
    int nsm = 148;
    cudaDeviceGetAttribute(&nsm, cudaDevAttrMultiProcessorCount, dev);

    uk<<<nsm, 1024>>>(x, ei, batch, W1, b1, W2, b2, W3, b3, W4, b4,
                      W5, b5, W6, b6, W7, b7, p1, p2, p3, Wl1, Wc, bc, out);
}

// round 16
// speedup vs baseline: 1.2285x; 1.0023x over previous
#include <cuda_runtime.h>
#include <math.h>

#define NN 8192
#define EE 262144
#define KK1 4096
#define KK2 2048
#define KK3 1024
#define NG 64

typedef unsigned int u32;
typedef unsigned long long u64;

constexpr int NWB2 = KK1 / 32;
constexpr int NWB4 = KK2 / 32;
constexpr int NWB6 = KK3 / 32;
constexpr int NSW2 = NWB2 / 32;
constexpr int NSW4 = NWB4 / 32;
constexpr int NSW6 = NWB6 / 32;

// ------------------------- workspace layout (float units) --------------------
constexpr size_t O_X1   = 0;                 constexpr size_t S_X1   = (size_t)NN*32;
constexpr size_t O_X2   = O_X1+S_X1;         constexpr size_t S_X2   = (size_t)KK1*32;
constexpr size_t O_X3   = O_X2+S_X2;         constexpr size_t S_X3   = (size_t)KK1*64;
constexpr size_t O_X4   = O_X3+S_X3;         constexpr size_t S_X4   = (size_t)KK2*64;
constexpr size_t O_X5   = O_X4+S_X4;         constexpr size_t S_X5   = (size_t)KK2*128;
constexpr size_t O_X6   = O_X5+S_X5;         constexpr size_t S_X6   = (size_t)KK3*128;
constexpr size_t O_X7   = O_X6+S_X6;         constexpr size_t S_X7   = (size_t)KK3*256;
constexpr size_t O_X9   = O_X7+S_X7;         constexpr size_t S_X9   = (size_t)KK2*128;
constexpr size_t O_X11  = O_X9+S_X9;         constexpr size_t S_X11  = (size_t)KK1*64;
constexpr size_t O_ZA   = O_X11+S_X11;       constexpr size_t S_ZA   = 262144;
constexpr size_t O_ZB   = O_ZA+S_ZA;         constexpr size_t S_ZB   = 262144;
constexpr size_t O_COL  = O_ZB+S_ZB;         constexpr size_t S_COL  = EE;
constexpr size_t O_DEG0 = O_COL+S_COL;       constexpr size_t S_DEG0 = NN;
constexpr size_t O_DINV0= O_DEG0+S_DEG0;     constexpr size_t S_DINV0= NN;
constexpr size_t O_DINV2= O_DINV0+S_DINV0;   constexpr size_t S_DINV2= KK1;
constexpr size_t O_DINV4= O_DINV2+S_DINV2;   constexpr size_t S_DINV4= KK2;
constexpr size_t O_DINV6= O_DINV4+S_DINV4;   constexpr size_t S_DINV6= KK3;
constexpr size_t O_S    = O_DINV6+S_DINV6;   constexpr size_t S_S    = NN;
constexpr size_t O_KEY  = O_S+S_S;           constexpr size_t S_KEY  = (size_t)NN*2;
constexpr size_t O_RANK = O_KEY+S_KEY;       constexpr size_t S_RANK = NN;
constexpr size_t O_POS0 = O_RANK+S_RANK;     constexpr size_t S_POS0 = NN;
constexpr size_t O_POS4 = O_POS0+S_POS0;     constexpr size_t S_POS4 = KK1;
constexpr size_t O_POS6 = O_POS4+S_POS4;     constexpr size_t S_POS6 = KK2;
constexpr size_t O_RP   = O_POS6+S_POS6;     constexpr size_t S_RP   = NN+8;
constexpr size_t O_OFF  = O_RP+S_RP;         constexpr size_t S_OFF  = NN;
constexpr size_t O_BM2  = O_OFF+S_OFF;       constexpr size_t S_BM2  = (size_t)KK1*NWB2;
constexpr size_t O_BM4  = O_BM2+S_BM2;       constexpr size_t S_BM4  = (size_t)KK2*NWB4;
constexpr size_t O_BM6  = O_BM4+S_BM4;       constexpr size_t S_BM6  = (size_t)KK3*NWB6;
constexpr size_t O_SUM2 = O_BM6+S_BM6;       constexpr size_t S_SUM2 = (size_t)KK1*NSW2;
constexpr size_t O_SUM4 = O_SUM2+S_SUM2;     constexpr size_t S_SUM4 = (size_t)KK2*NSW4;
constexpr size_t O_SUM6 = O_SUM4+S_SUM4;     constexpr size_t S_SUM6 = (size_t)KK3*NSW6;
constexpr size_t O_GSUM = O_SUM6+S_SUM6;     constexpr size_t S_GSUM = (size_t)NG*32;
constexpr size_t O_GMAX = O_GSUM+S_GSUM;     constexpr size_t S_GMAX = (size_t)NG*32;
constexpr size_t O_CNT  = O_GMAX+S_GMAX;     constexpr size_t S_CNT  = NG;
constexpr size_t WS_TOTAL = O_CNT + S_CNT;

__device__ __align__(256) float g_ws[WS_TOTAL];
__device__ unsigned g_arrive = 0;

// ------------------------------- helpers -------------------------------------
__device__ __forceinline__ float eluf(float x) { return x > 0.f ? x : expm1f(x); }
__device__ __forceinline__ unsigned ford(float f) {
    unsigned u = __float_as_uint(f);
    return (u & 0x80000000u) ? ~u : (u | 0x80000000u);
}
__device__ __forceinline__ float unford(unsigned u) {
    return __uint_as_float((u & 0x80000000u) ? (u & 0x7fffffffu) : ~u);
}

// chip-wide barrier: release-arrive / acquire-spin (1 block/SM)
__device__ __forceinline__ void gsync() {
    __syncthreads();
    if (threadIdx.x == 0) {
        unsigned t;
        asm volatile("atom.release.gpu.add.u32 %0, [%1], 1;"
                     : "=r"(t) : "l"(&g_arrive) : "memory");
        unsigned target = (t / gridDim.x + 1u) * gridDim.x;
        unsigned v;
        do {
            asm volatile("ld.acquire.gpu.u32 %0, [%1];"
                         : "=r"(v) : "l"(&g_arrive) : "memory");
        } while (v < target);
    }
    __syncthreads();
}

__device__ __forceinline__ void zerof(float* p, int n) {
    int gt = blockIdx.x * blockDim.x + threadIdx.x, NT = gridDim.x * blockDim.x;
    for (int i = gt; i < n; i += NT) p[i] = 0.f;
}

// ---------------------------- phase device funcs ------------------------------

__device__ __forceinline__ float a_elem(const float* __restrict__ X,
                                        const int* __restrict__ pos,
                                        const float* __restrict__ skip,
                                        int F1, int F2, int K, int gi, int kk) {
    if (!pos) return X[(size_t)gi * K + kk];
    if (kk < F1) {
        int p = pos[gi];
        return (p >= 0) ? eluf(X[(size_t)p * F1 + kk]) : 0.f;
    }
    return eluf(skip[(size_t)gi * F2 + (kk - F1)]);
}

// 128x64-tile GEMM, 1024 threads, 4x2 micro; KS-deep slabs, double-buffered
// smem (1 sync/slab); split-K atomicAdd accumulate. KS must divide K/SK.
template<int KS>
__device__ void gemm_dev(const float* __restrict__ X, const int* __restrict__ pos,
                         const float* __restrict__ skip, int F1, int F2,
                         const float* __restrict__ W, float* __restrict__ out,
                         int n, int K, int M, float* sh, int bstart, int bstride,
                         int SK) {
    constexpr int ABUF = KS * 132;
    constexpr int GB   = ABUF + KS * 66;
    constexpr int NA   = (128 * KS) / 1024;
    constexpr int NBW  = (64 * KS) / 1024;
    int tid = threadIdx.x;
    int tm = (tid >> 5) << 2;
    int tn = (tid & 31) << 1;
    int am = tid / KS, ak = tid % KS;
    int ntn = (M + 63) >> 6;
    int ntm = n >> 7;
    int ntile = ntm * ntn;
    int njobs = ntile * SK;
    int Kb = K / SK;
    for (int j = bstart; j < njobs; j += bstride) {
        int t = j % ntile, kh = j / ntile;
        int kbeg = kh * Kb, kend = kbeg + Kb;
        int bm = (t / ntn) << 7, bn = (t % ntn) << 6;
        float acc[4][2];
#pragma unroll
        for (int r = 0; r < 4; r++) { acc[r][0] = 0.f; acc[r][1] = 0.f; }
        float ra[NA], rb[NBW];
#pragma unroll
        for (int i = 0; i < NA; i++)
            ra[i] = a_elem(X, pos, skip, F1, F2, K, bm + am + i * (1024 / KS), kbeg + ak);
#pragma unroll
        for (int i = 0; i < NBW; i++) {
            int l = tid + i * 1024, bk = l >> 6, bj = l & 63;
            rb[i] = (bn + bj < M) ? W[(size_t)(kbeg + bk) * M + (bn + bj)] : 0.f;
        }
        int cur = 0;
        __syncthreads();
        for (int kk = kbeg; kk < kend; kk += KS) {
            float* As = sh + cur * GB;
            float* Bs = As + ABUF;
#pragma unroll
            for (int i = 0; i < NA; i++)
                As[ak * 132 + am + i * (1024 / KS)] = ra[i];
#pragma unroll
            for (int i = 0; i < NBW; i++) {
                int l = tid + i * 1024;
                Bs[(l >> 6) * 66 + (l & 63)] = rb[i];
            }
            __syncthreads();
            if (kk + KS < kend) {
#pragma unroll
                for (int i = 0; i < NA; i++)
                    ra[i] = a_elem(X, pos, skip, F1, F2, K,
                                   bm + am + i * (1024 / KS), kk + KS + ak);
#pragma unroll
                for (int i = 0; i < NBW; i++) {
                    int l = tid + i * 1024, bk = l >> 6, bj = l & 63;
                    rb[i] = (bn + bj < M) ? W[(size_t)(kk + KS + bk) * M + (bn + bj)] : 0.f;
                }
            }
#pragma unroll
            for (int k = 0; k < KS; k++) {
                float4 aa = *(const float4*)&As[k * 132 + tm];
                float2 bb = *(const float2*)&Bs[k * 66 + tn];
                acc[0][0] += aa.x * bb.x; acc[0][1] += aa.x * bb.y;
                acc[1][0] += aa.y * bb.x; acc[1][1] += aa.y * bb.y;
                acc[2][0] += aa.z * bb.x; acc[2][1] += aa.z * bb.y;
                acc[3][0] += aa.w * bb.x; acc[3][1] += aa.w * bb.y;
            }
            cur ^= 1;
        }
        int gi = bm + tm, gj = bn + tn;
        if (gj < M) {
#pragma unroll
            for (int r = 0; r < 4; r++)
                atomicAdd(&out[(size_t)(gi + r) * M + gj], acc[r][0]);
            if (gj + 1 < M) {
#pragma unroll
                for (int r = 0; r < 4; r++)
                    atomicAdd(&out[(size_t)(gi + r) * M + gj + 1], acc[r][1]);
            }
        }
    }
}

// 128x32-tile GEMM for M==32, 1024 threads, 4x1 micro; KS-deep slabs.
template<int KS>
__device__ void gemm32_dev(const float* __restrict__ X, const int* __restrict__ pos,
                           const float* __restrict__ skip, int F1, int F2,
                           const float* __restrict__ W, float* __restrict__ out,
                           int n, int K, float* sh, int bstart, int bstride,
                           int SK) {
    constexpr int ABUF = KS * 132;
    constexpr int GB   = ABUF + KS * 33;
    constexpr int NA   = (128 * KS) / 1024;
    int tid = threadIdx.x;
    int tm = (tid >> 5) << 2;
    int tn = tid & 31;
    int am = tid / KS, ak = tid % KS;
    int bactive = (tid < KS * 32);
    int bk = tid >> 5, bj = tid & 31;
    int ntm = n >> 7;
    int njobs = ntm * SK;
    int Kb = K / SK;
    for (int j = bstart; j < njobs; j += bstride) {
        int t = j % ntm, kh = j / ntm;
        int kbeg = kh * Kb, kend = kbeg + Kb;
        int bm = t << 7;
        float a0 = 0.f, a1 = 0.f, a2 = 0.f, a3 = 0.f;
        float ra[NA];
#pragma unroll
        for (int i = 0; i < NA; i++)
            ra[i] = a_elem(X, pos, skip, F1, F2, K, bm + am + i * (1024 / KS), kbeg + ak);
        float rb = bactive ? W[(size_t)(kbeg + bk) * 32 + bj] : 0.f;
        int cur = 0;
        __syncthreads();
        for (int kk = kbeg; kk < kend; kk += KS) {
            float* As = sh + cur * GB;
            float* Bs = As + ABUF;
#pragma unroll
            for (int i = 0; i < NA; i++)
                As[ak * 132 + am + i * (1024 / KS)] = ra[i];
            if (bactive) Bs[bk * 33 + bj] = rb;
            __syncthreads();
            if (kk + KS < kend) {
#pragma unroll
                for (int i = 0; i < NA; i++)
                    ra[i] = a_elem(X, pos, skip, F1, F2, K,
                                   bm + am + i * (1024 / KS), kk + KS + ak);
                rb = bactive ? W[(size_t)(kk + KS + bk) * 32 + bj] : 0.f;
            }
#pragma unroll
            for (int k = 0; k < KS; k++) {
                float4 aa = *(const float4*)&As[k * 132 + tm];
                float b  = Bs[k * 33 + tn];
                a0 += aa.x * b; a1 += aa.y * b;
                a2 += aa.z * b; a3 += aa.w * b;
            }
            cur ^= 1;
        }
        int gi = bm + tm;
        atomicAdd(&out[(size_t)gi * 32 + tn], a0);
        atomicAdd(&out[(size_t)(gi + 1) * 32 + tn], a1);
        atomicAdd(&out[(size_t)(gi + 2) * 32 + tn], a2);
        atomicAdd(&out[(size_t)(gi + 3) * 32 + tn], a3);
    }
}

// 64x64-tile GEMM, 1024 threads, 2x2 micro; double-buffered smem.
constexpr int GBUF64 = 16 * 66 + 16 * 66;
__device__ void gemm64_dev(const float* __restrict__ X,
                           const float* __restrict__ W, float* __restrict__ out,
                           int n, int K, int M, float* sh, int bstart, int bstride,
                           int SK) {
    int tid = threadIdx.x;
    int tm = (tid >> 5) << 1;
    int tn = (tid & 31) << 1;
    int lm = tid >> 4, lk = tid & 15;
    int bk = tid >> 6, bj = tid & 63;
    int ntn = (M + 63) >> 6;
    int ntm = n >> 6;
    int ntile = ntm * ntn;
    int njobs = ntile * SK;
    int Kb = K / SK;
    for (int j = bstart; j < njobs; j += bstride) {
        int t = j % ntile, kh = j / ntile;
        int kbeg = kh * Kb, kend = kbeg + Kb;
        int bm = (t / ntn) << 6, bn = (t % ntn) << 6;
        float a00 = 0.f, a01 = 0.f, a10 = 0.f, a11 = 0.f;
        float ra = X[(size_t)(bm + lm) * K + (kbeg + lk)];
        float rb = (bn + bj < M) ? W[(size_t)(kbeg + bk) * M + (bn + bj)] : 0.f;
        int cur = 0;
        __syncthreads();
        for (int kk = kbeg; kk < kend; kk += 16) {
            float* As = sh + cur * GBUF64;
            float* Bs = As + 16 * 66;
            As[lk * 66 + lm] = ra;
            Bs[bk * 66 + bj] = rb;
            __syncthreads();
            if (kk + 16 < kend) {
                ra = X[(size_t)(bm + lm) * K + (kk + 16 + lk)];
                rb = (bn + bj < M) ? W[(size_t)(kk + 16 + bk) * M + (bn + bj)] : 0.f;
            }
#pragma unroll
            for (int k = 0; k < 16; k++) {
                float2 aa = *(const float2*)&As[k * 66 + tm];
                float2 bb = *(const float2*)&Bs[k * 66 + tn];
                a00 += aa.x * bb.x; a01 += aa.x * bb.y;
                a10 += aa.y * bb.x; a11 += aa.y * bb.y;
            }
            cur ^= 1;
        }
        int gi = bm + tm, gj = bn + tn;
        if (gj < M) {
            atomicAdd(&out[(size_t)gi * M + gj], a00);
            atomicAdd(&out[(size_t)(gi + 1) * M + gj], a10);
            if (gj + 1 < M) {
                atomicAdd(&out[(size_t)gi * M + gj + 1], a01);
                atomicAdd(&out[(size_t)(gi + 1) * M + gj + 1], a11);
            }
        }
    }
}

// rank: 2048-row i-tiles, 2 rows per thread; CH-wide j-chunks in smem,
// vectorized ulonglong2 loads (CH even).
__device__ void rank_dev(const u64* __restrict__ key, int n, int CH,
                         int* __restrict__ rank, u64* shk) {
    int nti = n >> 11;
    int ntj = n / CH;
    for (int t = blockIdx.x; t < nti * ntj; t += gridDim.x) {
        int ti = t / ntj, tj = t - ti * ntj;
        int i0 = (ti << 11) + threadIdx.x;
        int j0 = tj * CH;
        __syncthreads();
        for (int l = threadIdx.x; l < CH; l += 1024) shk[l] = key[j0 + l];
        __syncthreads();
        u64 ka = key[i0], kb = key[i0 + 1024];
        int ca = 0, cb = 0;
        const ulonglong2* shk2 = (const ulonglong2*)shk;
#pragma unroll 4
        for (int j = 0; j < CH / 2; j++) {
            ulonglong2 kk = shk2[j];
            ca += (kk.x > ka) ? 1 : 0;
            ca += (kk.y > ka) ? 1 : 0;
            cb += (kk.x > kb) ? 1 : 0;
            cb += (kk.y > kb) ? 1 : 0;
        }
        if (ca) atomicAdd(&rank[i0], ca);
        if (cb) atomicAdd(&rank[i0 + 1024], cb);
    }
}

__device__ void gather_dev(const float* __restrict__ x, const float* __restrict__ s,
                           const int* __restrict__ rank, int n, int k, int F,
                           float* __restrict__ out, int* __restrict__ pos) {
    int gt = blockIdx.x * blockDim.x + threadIdx.x, NT = gridDim.x * blockDim.x;
    for (int t = gt; t < n * F; t += NT) {
        int i = t / F, f = t - i * F;
        int r = rank[i];
        if (f == 0) pos[i] = (r < k) ? r : -1;
        if (r < k) {
            float gate = 1.f / (1.f + expf(-s[i]));
            out[(size_t)r * F + f] = eluf(x[t] * gate);
        }
    }
}

__device__ void bmfilter_dev(const u32* __restrict__ bms, const u32* __restrict__ ssum,
                             int nws, int nssw, int nsrc, const int* __restrict__ rank,
                             int k, int nwd, u32* __restrict__ bmd) {
    int lane = threadIdx.x & 31;
    int wg = (blockIdx.x * blockDim.x + threadIdx.x) >> 5;
    int NWp = (gridDim.x * blockDim.x) >> 5;
    for (int i = wg; i < nsrc; i += NWp) {
        int b = rank[i];
        if (b >= k) continue;
        const u32* row = bms + (size_t)i * nws;
        const u32* srow = ssum + (size_t)i * nssw;
        for (int w = lane; w < nws; w += 32) {
            if (!((srow[w >> 5] >> (w & 31)) & 1u)) continue;
            u32 word = row[w];
            while (word) {
                int bit = __ffs(word) - 1; word &= word - 1;
                int ps = rank[(w << 5) + bit];
                if (ps < k) atomicOr(&bmd[(size_t)b * nwd + (ps >> 5)], 1u << (ps & 31));
            }
        }
    }
}

__device__ void dinvsum_dev(const u32* __restrict__ bm, int n, int nw, int nsw,
                            float* __restrict__ dv, u32* __restrict__ sum) {
    int lane = threadIdx.x & 31;
    int wg = (blockIdx.x * blockDim.x + threadIdx.x) >> 5;
    int NWp = (gridDim.x * blockDim.x) >> 5;
    for (int r = wg; r < n; r += NWp) {
        int c = 0;
        for (int g = 0; g < nsw; g++) {
            u32 word = bm[(size_t)r * nw + (g << 5) + lane];
            u32 m = __ballot_sync(0xffffffffu, word != 0u);
            c += __popc(word);
            if (lane == 0) sum[(size_t)r * nsw + g] = m;
        }
#pragma unroll
        for (int o = 16; o > 0; o >>= 1) c += __shfl_xor_sync(0xffffffffu, c, o);
        if (lane == 0) dv[r] = rsqrtf((float)(c + 1));
    }
}

// bitmap SpMM; NSEG column segments per row (parallelism for small n);
// neighbors batch-decoded (NB at a time). Score fusion requires NSEG==1.
template<int FW, int NSEG>
__device__ void spmm_dev(const u32* __restrict__ bm, const u32* __restrict__ sum,
                         int nw, int nsw, const float* __restrict__ z,
                         const float* __restrict__ dv, const float* __restrict__ bias,
                         float* __restrict__ out, int n,
                         const float* __restrict__ p, float* __restrict__ ss,
                         u64* __restrict__ key) {
    const int F = FW * 32 * NSEG;
    const int NB = (FW <= 4) ? 4 : 2;
    int lane = threadIdx.x & 31;
    int wg = (blockIdx.x * blockDim.x + threadIdx.x) >> 5;
    int NWp = (gridDim.x * blockDim.x) >> 5;
    float invn = 0.f;
    float pl[FW];
    if (p && NSEG == 1) {
        float q = 0.f;
#pragma unroll
        for (int c = 0; c < FW; c++) { pl[c] = p[lane + 32 * c]; q += pl[c] * pl[c]; }
#pragma unroll
        for (int o = 16; o > 0; o >>= 1) q += __shfl_xor_sync(0xffffffffu, q, o);
        invn = rsqrtf(q);
    }
    for (int t = wg; t < n * NSEG; t += NWp) {
        int r  = (NSEG == 1) ? t : (t / NSEG);
        int co = (NSEG == 1) ? 0 : ((t - r * NSEG) * FW * 32);
        float dr = dv[r];
        float acc[FW];
#pragma unroll
        for (int c = 0; c < FW; c++)
            acc[c] = dr * z[(size_t)r * F + co + lane + 32 * c];
        const u32* row = bm + (size_t)r * nw;
        const u32* srow = sum + (size_t)r * nsw;
        int nbuf[NB];
        int m = 0;
        auto flush = [&](int mc) {
            float dvs[NB];
            float tmp[NB][FW];
#pragma unroll
            for (int i = 0; i < NB; i++) if (i < mc) dvs[i] = dv[nbuf[i]];
#pragma unroll
            for (int i = 0; i < NB; i++) if (i < mc) {
                const float* zs = z + (size_t)nbuf[i] * F + co + lane;
#pragma unroll
                for (int c = 0; c < FW; c++) tmp[i][c] = zs[32 * c];
            }
#pragma unroll
            for (int i = 0; i < NB; i++) if (i < mc)
#pragma unroll
                for (int c = 0; c < FW; c++) acc[c] += dvs[i] * tmp[i][c];
        };
        for (int sw = 0; sw < nsw; sw++) {
            u32 sword = srow[sw];
            while (sword) {
                int wb = __ffs(sword) - 1; sword &= sword - 1;
                int w = (sw << 5) + wb;
                u32 word = row[w];
                while (word) {
                    int b = __ffs(word) - 1; word &= word - 1;
                    nbuf[m++] = (w << 5) + b;
                    if (m == NB) { flush(NB); m = 0; }
                }
            }
        }
        if (m) flush(m);
        float sc = 0.f;
#pragma unroll
        for (int c = 0; c < FW; c++) {
            float v = eluf(dr * acc[c] + bias[co + lane + 32 * c]);
            out[(size_t)r * F + co + lane + 32 * c] = v;
            if (p && NSEG == 1) sc += v * pl[c];
        }
        if (p && NSEG == 1) {
#pragma unroll
            for (int o = 16; o > 0; o >>= 1) sc += __shfl_xor_sync(0xffffffffu, sc, o);
            if (lane == 0) {
                float sv = sc * invn;
                ss[r] = sv;
                key[r] = ((u64)ford(sv) << 32) | (u32)(~r);
            }
        }
    }
}

__device__ void csragg_dev(const float* __restrict__ z, const int* __restrict__ rp,
                           const int* __restrict__ col, const float* __restrict__ dv,
                           const float* __restrict__ bias, float* __restrict__ out,
                           const float* __restrict__ p, float* __restrict__ ss,
                           u64* __restrict__ key,
                           const int* __restrict__ batch, float* __restrict__ gsum,
                           u32* __restrict__ gmax, float* __restrict__ cnt) {
    int lane = threadIdx.x & 31;
    int wg = (blockIdx.x * blockDim.x + threadIdx.x) >> 5;
    int NWp = (gridDim.x * blockDim.x) >> 5;
    float invn = 0.f, pv = 0.f;
    if (p) {
        pv = p[lane];
        float q = pv * pv;
#pragma unroll
        for (int o = 16; o > 0; o >>= 1) q += __shfl_xor_sync(0xffffffffu, q, o);
        invn = rsqrtf(q);
    }
    float bl = bias[lane];
    for (int r = wg; r < NN; r += NWp) {
        float dr = dv[r];
        float acc = dr * z[r * 32 + lane];
        int e = rp[r], e1 = rp[r + 1];
        for (; e + 7 < e1; e += 8) {
            int s[8]; float d[8], v[8];
#pragma unroll
            for (int i = 0; i < 8; i++) s[i] = col[e + i];
#pragma unroll
            for (int i = 0; i < 8; i++) { d[i] = dv[s[i]]; v[i] = z[s[i] * 32 + lane]; }
#pragma unroll
            for (int i = 0; i < 8; i++) acc += d[i] * v[i];
        }
        for (; e < e1; e++) { int s = col[e]; acc += dv[s] * z[s * 32 + lane]; }
        float val = eluf(dr * acc + bl);
        if (out) {
            out[r * 32 + lane] = val;
            if (p) {
                float sc = val * pv;
#pragma unroll
                for (int o = 16; o > 0; o >>= 1) sc += __shfl_xor_sync(0xffffffffu, sc, o);
                if (lane == 0) {
                    float sv = sc * invn;
                    ss[r] = sv;
                    key[r] = ((u64)ford(sv) << 32) | (u32)(~r);
                }
            }
        } else {
            int g = batch[r];
            atomicAdd(&gsum[g * 32 + lane], val);
            atomicMax(&gmax[g * 32 + lane], ford(val));
            if (lane == 0) atomicAdd(&cnt[g], 1.f);
        }
    }
}

// --------------------------------- megakernel --------------------------------
__global__ void __launch_bounds__(1024, 1)
uk(const float* __restrict__ x, const int* __restrict__ ei, const int* __restrict__ batch,
   const float* W1, const float* b1, const float* W2, const float* b2,
   const float* W3, const float* b3, const float* W4, const float* b4,
   const float* W5, const float* b5, const float* W6, const float* b6,
   const float* W7, const float* b7, const float* p1, const float* p2, const float* p3,
   const float* Wl1, const float* Wc, const float* bc, float* __restrict__ out) {
    __shared__ __align__(16) float sh[12800];
    float* B = g_ws;
    float* ZA  = B + O_ZA;
    float* ZB  = B + O_ZB;
    int*  COL  = (int*)(B + O_COL);
    int*  DEG0 = (int*)(B + O_DEG0);
    float* DV0 = B + O_DINV0;
    float* DV2 = B + O_DINV2;
    float* DV4 = B + O_DINV4;
    float* DV6 = B + O_DINV6;
    float* SS  = B + O_S;
    u64*  KEY  = (u64*)(B + O_KEY);
    int*  RANK = (int*)(B + O_RANK);
    int*  POS0 = (int*)(B + O_POS0);
    int*  POS4 = (int*)(B + O_POS4);
    int*  POS6 = (int*)(B + O_POS6);
    int*  RP   = (int*)(B + O_RP);
    int*  OFF  = (int*)(B + O_OFF);
    u32*  BM2  = (u32*)(B + O_BM2);
    u32*  BM4  = (u32*)(B + O_BM4);
    u32*  BM6  = (u32*)(B + O_BM6);
    u32*  SUM2 = (u32*)(B + O_SUM2);
    u32*  SUM4 = (u32*)(B + O_SUM4);
    u32*  SUM6 = (u32*)(B + O_SUM6);
    float* GSUM= B + O_GSUM;
    u32*  GMAX = (u32*)(B + O_GMAX);
    float* CNT = B + O_CNT;

    int tid = threadIdx.x;
    int gt  = blockIdx.x * 1024 + tid;
    int NT  = gridDim.x * 1024;

    // B1: degree histogram (DEG0 zero by contract) ; prologue zeroing
    for (int e = gt; e < EE; e += NT) atomicAdd(&DEG0[ei[EE + e]], 1);
    for (int i = gt; i < KK1 * NWB2; i += NT) BM2[i] = 0;
    for (int i = gt; i < NG * 32; i += NT) { GSUM[i] = 0.f; GMAX[i] = 0u; }
    for (int i = gt; i < NG; i += NT) CNT[i] = 0.f;
    zerof(ZA, NN * 32);
    zerof(ZB, KK1 * 64);
    gsync();

    // B2: block 0 CSR scan || GEMM1 splitK2 (ZA, M=32 path, KS=32)
    if (blockIdx.x == 0) {
        int base = tid * 8;
        int s = 0;
#pragma unroll
        for (int j = 0; j < 8; j++) s += DEG0[base + j];
        int* shi = (int*)sh;
        shi[tid] = s;
        __syncthreads();
        for (int o = 1; o < 1024; o <<= 1) {
            int v = (tid >= o) ? shi[tid - o] : 0;
            __syncthreads();
            shi[tid] += v;
            __syncthreads();
        }
        int run = shi[tid] - s;
#pragma unroll
        for (int j = 0; j < 8; j++) {
            int d = DEG0[base + j];
            RP[base + j] = run;
            OFF[base + j] = run;
            DV0[base + j] = rsqrtf((float)(d + 1));
            run += d;
        }
        if (tid == 1023) RP[NN] = run;
    } else {
        gemm32_dev<32>(x, nullptr, nullptr, 0, 0, W1, ZA, NN, 128, sh,
                       blockIdx.x - 1, gridDim.x - 1, 2);
    }
    gsync();

    // B3: CSR scatter ; re-zero DEG0
    for (int e = gt; e < EE; e += NT) {
        int s = ei[e], d = ei[EE + e];
        int pp = atomicAdd(&OFF[d], 1);
        COL[pp] = s;
    }
    for (int i = gt; i < NN; i += NT) DEG0[i] = 0;
    gsync();

    // B4: X1 = csragg(ZA) + score1/key ; zero RANK
    csragg_dev(ZA, RP, COL, DV0, b1, B + O_X1, p1, SS, KEY,
               nullptr, nullptr, nullptr, nullptr);
    for (int i = gt; i < NN; i += NT) RANK[i] = 0;
    gsync();

    // B5: rank pool1 (128 tiles)
    rank_dev(KEY, NN, 256, RANK, (u64*)sh);
    gsync();

    // B6: gather1 -> X2 ; bm_edges -> BM2 ; zero BM4
    gather_dev(B + O_X1, SS, RANK, NN, KK1, 32, B + O_X2, POS0);
    for (int e = gt; e < EE; e += NT) {
        int rs = RANK[ei[e]], rd = RANK[ei[EE + e]];
        if (rs < KK1 && rd < KK1)
            atomicOr(&BM2[(size_t)rd * NWB2 + (rs >> 5)], 1u << (rs & 31));
    }
    for (int i = gt; i < KK2 * NWB4; i += NT) BM4[i] = 0;
    gsync();

    // B7: GEMM2 splitK2 (ZB, 64x64: 128 jobs) || dinvsum2
    gemm64_dev(B + O_X2, W2, ZB, KK1, 32, 64, sh, blockIdx.x, gridDim.x, 2);
    dinvsum_dev(BM2, KK1, NWB2, NSW2, DV2, SUM2);
    gsync();

    // B8: spmm2(ZB) -> X3 + score2 ; zero RANK ; zero ZA (GEMM3)
    spmm_dev<2, 1>(BM2, SUM2, NWB2, NSW2, ZB, DV2, b2, B + O_X3, KK1, p2, SS, KEY);
    for (int i = gt; i < KK1; i += NT) RANK[i] = 0;
    zerof(ZA, KK2 * 128);
    gsync();

    // B9: rank pool2 (128 tiles)
    rank_dev(KEY, KK1, 64, RANK, (u64*)sh);
    gsync();

    // B10: gather2 -> X4 ; bmfilter BM2->BM4 ; zero BM6
    gather_dev(B + O_X3, SS, RANK, KK1, KK2, 64, B + O_X4, POS4);
    bmfilter_dev(BM2, SUM2, NWB2, NSW2, KK1, RANK, KK2, NWB4, BM4);
    for (int i = gt; i < KK3 * NWB6; i += NT) BM6[i] = 0;
    gsync();

    // B11: GEMM3 splitK4 (ZA, KS=16) || dinvsum4
    gemm_dev<16>(B + O_X4, nullptr, nullptr, 0, 0, W3, ZA, KK2, 64, 128, sh,
                 blockIdx.x, gridDim.x, 4);
    dinvsum_dev(BM4, KK2, NWB4, NSW4, DV4, SUM4);
    gsync();

    // B12: spmm3(ZA) -> X5 + score3 ; zero RANK ; zero ZB (GEMM4)
    spmm_dev<4, 1>(BM4, SUM4, NWB4, NSW4, ZA, DV4, b3, B + O_X5, KK2, p3, SS, KEY);
    for (int i = gt; i < KK2; i += NT) RANK[i] = 0;
    zerof(ZB, KK3 * 256);
    gsync();

    // B13: rank pool3 (128 tiles, CH=16)
    rank_dev(KEY, KK2, 16, RANK, (u64*)sh);
    gsync();

    // B14: gather3 -> X6 ; bmfilter BM4->BM6
    gather_dev(B + O_X5, SS, RANK, KK2, KK3, 128, B + O_X6, POS6);
    bmfilter_dev(BM4, SUM4, NWB4, NSW4, KK2, RANK, KK3, NWB6, BM6);
    gsync();

    // B15: GEMM4 splitK4 (ZB, KS=32: 1 slab) || dinvsum6
    gemm_dev<32>(B + O_X6, nullptr, nullptr, 0, 0, W4, ZB, KK3, 128, 256, sh,
                 blockIdx.x, gridDim.x, 4);
    dinvsum_dev(BM6, KK3, NWB6, NSW6, DV6, SUM6);
    gsync();

    // B16: spmm4(ZB) -> X7 (4 col-segments: 4096 warp-tasks) ; zero ZA (GEMM5)
    spmm_dev<2, 4>(BM6, SUM6, NWB6, NSW6, ZB, DV6, b4, B + O_X7, KK3,
                   nullptr, nullptr, nullptr);
    zerof(ZA, KK2 * 128);
    gsync();

    // B17: GEMM5 splitK4 (ZA, KS=32: 3 slabs) fused concat(X7/POS6, X5)
    gemm_dev<32>(B + O_X7, POS6, B + O_X5, 256, 128, W5, ZA, KK2, 384, 128, sh,
                 blockIdx.x, gridDim.x, 4);
    gsync();

    // B18: spmm5(ZA) -> X9 (2 col-segments: 4096 warp-tasks) ; zero ZB (GEMM6)
    spmm_dev<2, 2>(BM4, SUM4, NWB4, NSW4, ZA, DV4, b5, B + O_X9, KK2,
                   nullptr, nullptr, nullptr);
    zerof(ZB, KK1 * 64);
    gsync();

    // B19: GEMM6 splitK4 (ZB, KS=16: 3 slabs) fused concat(X9/POS4, X3)
    gemm_dev<16>(B + O_X9, POS4, B + O_X3, 128, 64, W6, ZB, KK1, 192, 64, sh,
                 blockIdx.x, gridDim.x, 4);
    gsync();

    // B20: spmm6(ZB) -> X11 ; zero ZA (GEMM7)
    spmm_dev<2, 1>(BM2, SUM2, NWB2, NSW2, ZB, DV2, b6, B + O_X11, KK1,
                   nullptr, nullptr, nullptr);
    zerof(ZA, NN * 32);
    gsync();

    // B21: GEMM7 splitK2 (ZA, M=32 path, KS=16) fused concat(X11/POS0, X1)
    gemm32_dev<16>(B + O_X11, POS0, B + O_X1, 64, 32, W7, ZA, NN, 96, sh,
                   blockIdx.x, gridDim.x, 2);
    gsync();

    // B22: final csragg(ZA) with fused readout
    csragg_dev(ZA, RP, COL, DV0, b7, nullptr, nullptr, nullptr, nullptr,
               batch, GSUM, GMAX, CNT);
    gsync();

    // ---- head ----
    if (blockIdx.x < NG) {
        int g = blockIdx.x;
        float* h  = sh;
        float* h2 = sh + 64;
        float* lg = sh + 128;
        if (tid < 64)
            h[tid] = eluf(tid < 32 ? unford(GMAX[g * 32 + tid])
                                   : GSUM[g * 32 + (tid - 32)] / CNT[g]);
        __syncthreads();
        if (tid < 64) {
            float acc = 0.f;
#pragma unroll
            for (int k = 0; k < 64; k++) acc += h[k] * Wl1[k * 64 + tid];
            h2[tid] = eluf(acc);
        }
        __syncthreads();
        if (tid < 10) {
            float a = bc[tid];
#pragma unroll
            for (int k = 0; k < 64; k++) a += h2[k] * Wc[k * 10 + tid];
            lg[tid] = a;
        }
        __syncthreads();
        if (tid == 0) {
            float m = lg[0];
            for (int c = 1; c < 10; c++) m = fmaxf(m, lg[c]);
            float se = 0.f;
            for (int c = 0; c < 10; c++) se += expf(lg[c] - m);
            sh[140] = m + logf(se);
        }
        __syncthreads();
        if (tid < 10) out[g * 10 + tid] = lg[tid] - sh[140];
    }
}

// ------------------------------- launcher ------------------------------------
extern "C" void kernel_launch(void* const* d_in, const int* in_sizes, int n_in,
                              void* d_out, int out_size) {
    (void)in_sizes; (void)n_in; (void)out_size;
    const float* x    = (const float*)d_in[0];
    const int*   ei   = (const int*)d_in[1];
    const int*   batch= (const int*)d_in[2];
    const float* W1 = (const float*)d_in[3],  *b1 = (const float*)d_in[4];
    const float* W2 = (const float*)d_in[5],  *b2 = (const float*)d_in[6];
    const float* W3 = (const float*)d_in[7],  *b3 = (const float*)d_in[8];
    const float* W4 = (const float*)d_in[9],  *b4 = (const float*)d_in[10];
    const float* W5 = (const float*)d_in[11], *b5 = (const float*)d_in[12];
    const float* W6 = (const float*)d_in[13], *b6 = (const float*)d_in[14];
    const float* W7 = (const float*)d_in[15], *b7 = (const float*)d_in[16];
    const float* p1 = (const float*)d_in[17];
    const float* p2 = (const float*)d_in[18];
    const float* p3 = (const float*)d_in[19];
    const float* Wl1= (const float*)d_in[20];
    const float* Wc = (const float*)d_in[21];
    const float* bc = (const float*)d_in[22];
    float* out = (float*)d_out;

    int dev = 0;
    cudaGetDevice(&dev);
    int nsm = 148;
    cudaDeviceGetAttribute(&nsm, cudaDevAttrMultiProcessorCount, dev);

    uk<<<nsm, 1024>>>(x, ei, batch, W1, b1, W2, b2, W3, b3, W4, b4,
                      W5, b5, W6, b6, W7, b7, p1, p2, p3, Wl1, Wc, bc, out);
}

// round 17
// speedup vs baseline: 1.2389x; 1.0084x over previous
#include <cuda_runtime.h>
#include <math.h>

#define NN 8192
#define EE 262144
#define KK1 4096
#define KK2 2048
#define KK3 1024
#define NG 64

typedef unsigned int u32;
typedef unsigned long long u64;

constexpr int NWB2 = KK1 / 32;
constexpr int NWB4 = KK2 / 32;
constexpr int NWB6 = KK3 / 32;
constexpr int NSW2 = NWB2 / 32;
constexpr int NSW4 = NWB4 / 32;
constexpr int NSW6 = NWB6 / 32;

// ------------------------- workspace layout (float units) --------------------
constexpr size_t O_X1   = 0;                 constexpr size_t S_X1   = (size_t)NN*32;
constexpr size_t O_X2   = O_X1+S_X1;         constexpr size_t S_X2   = (size_t)KK1*32;
constexpr size_t O_X3   = O_X2+S_X2;         constexpr size_t S_X3   = (size_t)KK1*64;
constexpr size_t O_X4   = O_X3+S_X3;         constexpr size_t S_X4   = (size_t)KK2*64;
constexpr size_t O_X5   = O_X4+S_X4;         constexpr size_t S_X5   = (size_t)KK2*128;
constexpr size_t O_X6   = O_X5+S_X5;         constexpr size_t S_X6   = (size_t)KK3*128;
constexpr size_t O_X7   = O_X6+S_X6;         constexpr size_t S_X7   = (size_t)KK3*256;
constexpr size_t O_X9   = O_X7+S_X7;         constexpr size_t S_X9   = (size_t)KK2*128;
constexpr size_t O_X11  = O_X9+S_X9;         constexpr size_t S_X11  = (size_t)KK1*64;
constexpr size_t O_ZA   = O_X11+S_X11;       constexpr size_t S_ZA   = 262144;
constexpr size_t O_ZB   = O_ZA+S_ZA;         constexpr size_t S_ZB   = 262144;
constexpr size_t O_COL  = O_ZB+S_ZB;         constexpr size_t S_COL  = EE;
constexpr size_t O_DEG0 = O_COL+S_COL;       constexpr size_t S_DEG0 = NN;
constexpr size_t O_DINV0= O_DEG0+S_DEG0;     constexpr size_t S_DINV0= NN;
constexpr size_t O_DINV2= O_DINV0+S_DINV0;   constexpr size_t S_DINV2= KK1;
constexpr size_t O_DINV4= O_DINV2+S_DINV2;   constexpr size_t S_DINV4= KK2;
constexpr size_t O_DINV6= O_DINV4+S_DINV4;   constexpr size_t S_DINV6= KK3;
constexpr size_t O_S    = O_DINV6+S_DINV6;   constexpr size_t S_S    = NN;
constexpr size_t O_KEY  = O_S+S_S;           constexpr size_t S_KEY  = (size_t)NN*2;
constexpr size_t O_RANK = O_KEY+S_KEY;       constexpr size_t S_RANK = NN;
constexpr size_t O_POS0 = O_RANK+S_RANK;     constexpr size_t S_POS0 = NN;
constexpr size_t O_POS4 = O_POS0+S_POS0;     constexpr size_t S_POS4 = KK1;
constexpr size_t O_POS6 = O_POS4+S_POS4;     constexpr size_t S_POS6 = KK2;
constexpr size_t O_RP   = O_POS6+S_POS6;     constexpr size_t S_RP   = NN+8;
constexpr size_t O_OFF  = O_RP+S_RP;         constexpr size_t S_OFF  = NN;
constexpr size_t O_BM2  = O_OFF+S_OFF;       constexpr size_t S_BM2  = (size_t)KK1*NWB2;
constexpr size_t O_BM4  = O_BM2+S_BM2;       constexpr size_t S_BM4  = (size_t)KK2*NWB4;
constexpr size_t O_BM6  = O_BM4+S_BM4;       constexpr size_t S_BM6  = (size_t)KK3*NWB6;
constexpr size_t O_SUM2 = O_BM6+S_BM6;       constexpr size_t S_SUM2 = (size_t)KK1*NSW2;
constexpr size_t O_SUM4 = O_SUM2+S_SUM2;     constexpr size_t S_SUM4 = (size_t)KK2*NSW4;
constexpr size_t O_SUM6 = O_SUM4+S_SUM4;     constexpr size_t S_SUM6 = (size_t)KK3*NSW6;
constexpr size_t O_GSUM = O_SUM6+S_SUM6;     constexpr size_t S_GSUM = (size_t)NG*32;
constexpr size_t O_GMAX = O_GSUM+S_GSUM;     constexpr size_t S_GMAX = (size_t)NG*32;
constexpr size_t O_CNT  = O_GMAX+S_GMAX;     constexpr size_t S_CNT  = NG;
constexpr size_t WS_TOTAL = O_CNT + S_CNT;

__device__ __align__(256) float g_ws[WS_TOTAL];
__device__ unsigned g_arrive = 0;

// ------------------------------- helpers -------------------------------------
__device__ __forceinline__ float eluf(float x) { return x > 0.f ? x : expm1f(x); }
__device__ __forceinline__ unsigned ford(float f) {
    unsigned u = __float_as_uint(f);
    return (u & 0x80000000u) ? ~u : (u | 0x80000000u);
}
__device__ __forceinline__ float unford(unsigned u) {
    return __uint_as_float((u & 0x80000000u) ? (u & 0x7fffffffu) : ~u);
}

// chip-wide barrier: release-arrive / acquire-spin (1 block/SM)
__device__ __forceinline__ void gsync() {
    __syncthreads();
    if (threadIdx.x == 0) {
        unsigned t;
        asm volatile("atom.release.gpu.add.u32 %0, [%1], 1;"
                     : "=r"(t) : "l"(&g_arrive) : "memory");
        unsigned target = (t / gridDim.x + 1u) * gridDim.x;
        unsigned v;
        do {
            asm volatile("ld.acquire.gpu.u32 %0, [%1];"
                         : "=r"(v) : "l"(&g_arrive) : "memory");
        } while (v < target);
    }
    __syncthreads();
}

__device__ __forceinline__ void zerof(float* p, int n) {
    int gt = blockIdx.x * blockDim.x + threadIdx.x, NT = gridDim.x * blockDim.x;
    for (int i = gt; i < n; i += NT) p[i] = 0.f;
}

// ---------------------------- phase device funcs ------------------------------

__device__ __forceinline__ float a_elem(const float* __restrict__ X,
                                        const int* __restrict__ pos,
                                        const float* __restrict__ skip,
                                        int F1, int F2, int K, int gi, int kk) {
    if (!pos) return X[(size_t)gi * K + kk];
    if (kk < F1) {
        int p = pos[gi];
        return (p >= 0) ? eluf(X[(size_t)p * F1 + kk]) : 0.f;
    }
    return eluf(skip[(size_t)gi * F2 + (kk - F1)]);
}

// 128x64-tile GEMM, 1024 threads, 4x2 micro; KS-deep slabs, double-buffered
// smem (1 sync/slab); split-K atomicAdd accumulate. KS must divide K/SK.
template<int KS>
__device__ void gemm_dev(const float* __restrict__ X, const int* __restrict__ pos,
                         const float* __restrict__ skip, int F1, int F2,
                         const float* __restrict__ W, float* __restrict__ out,
                         int n, int K, int M, float* sh, int bstart, int bstride,
                         int SK) {
    constexpr int ABUF = KS * 132;
    constexpr int GB   = ABUF + KS * 66;
    constexpr int NA   = (128 * KS) / 1024;
    constexpr int NBW  = (64 * KS) / 1024;
    int tid = threadIdx.x;
    int tm = (tid >> 5) << 2;
    int tn = (tid & 31) << 1;
    int am = tid / KS, ak = tid % KS;
    int ntn = (M + 63) >> 6;
    int ntm = n >> 7;
    int ntile = ntm * ntn;
    int njobs = ntile * SK;
    int Kb = K / SK;
    for (int j = bstart; j < njobs; j += bstride) {
        int t = j % ntile, kh = j / ntile;
        int kbeg = kh * Kb, kend = kbeg + Kb;
        int bm = (t / ntn) << 7, bn = (t % ntn) << 6;
        float acc[4][2];
#pragma unroll
        for (int r = 0; r < 4; r++) { acc[r][0] = 0.f; acc[r][1] = 0.f; }
        float ra[NA], rb[NBW];
#pragma unroll
        for (int i = 0; i < NA; i++)
            ra[i] = a_elem(X, pos, skip, F1, F2, K, bm + am + i * (1024 / KS), kbeg + ak);
#pragma unroll
        for (int i = 0; i < NBW; i++) {
            int l = tid + i * 1024, bk = l >> 6, bj = l & 63;
            rb[i] = (bn + bj < M) ? W[(size_t)(kbeg + bk) * M + (bn + bj)] : 0.f;
        }
        int cur = 0;
        __syncthreads();
        for (int kk = kbeg; kk < kend; kk += KS) {
            float* As = sh + cur * GB;
            float* Bs = As + ABUF;
#pragma unroll
            for (int i = 0; i < NA; i++)
                As[ak * 132 + am + i * (1024 / KS)] = ra[i];
#pragma unroll
            for (int i = 0; i < NBW; i++) {
                int l = tid + i * 1024;
                Bs[(l >> 6) * 66 + (l & 63)] = rb[i];
            }
            __syncthreads();
            if (kk + KS < kend) {
#pragma unroll
                for (int i = 0; i < NA; i++)
                    ra[i] = a_elem(X, pos, skip, F1, F2, K,
                                   bm + am + i * (1024 / KS), kk + KS + ak);
#pragma unroll
                for (int i = 0; i < NBW; i++) {
                    int l = tid + i * 1024, bk = l >> 6, bj = l & 63;
                    rb[i] = (bn + bj < M) ? W[(size_t)(kk + KS + bk) * M + (bn + bj)] : 0.f;
                }
            }
#pragma unroll
            for (int k = 0; k < KS; k++) {
                float4 aa = *(const float4*)&As[k * 132 + tm];
                float2 bb = *(const float2*)&Bs[k * 66 + tn];
                acc[0][0] += aa.x * bb.x; acc[0][1] += aa.x * bb.y;
                acc[1][0] += aa.y * bb.x; acc[1][1] += aa.y * bb.y;
                acc[2][0] += aa.z * bb.x; acc[2][1] += aa.z * bb.y;
                acc[3][0] += aa.w * bb.x; acc[3][1] += aa.w * bb.y;
            }
            cur ^= 1;
        }
        int gi = bm + tm, gj = bn + tn;
        if (gj < M) {
#pragma unroll
            for (int r = 0; r < 4; r++)
                atomicAdd(&out[(size_t)(gi + r) * M + gj], acc[r][0]);
            if (gj + 1 < M) {
#pragma unroll
                for (int r = 0; r < 4; r++)
                    atomicAdd(&out[(size_t)(gi + r) * M + gj + 1], acc[r][1]);
            }
        }
    }
}

// 128x32-tile GEMM for M==32, 1024 threads, 4x1 micro; KS-deep slabs.
template<int KS>
__device__ void gemm32_dev(const float* __restrict__ X, const int* __restrict__ pos,
                           const float* __restrict__ skip, int F1, int F2,
                           const float* __restrict__ W, float* __restrict__ out,
                           int n, int K, float* sh, int bstart, int bstride,
                           int SK) {
    constexpr int ABUF = KS * 132;
    constexpr int GB   = ABUF + KS * 33;
    constexpr int NA   = (128 * KS) / 1024;
    int tid = threadIdx.x;
    int tm = (tid >> 5) << 2;
    int tn = tid & 31;
    int am = tid / KS, ak = tid % KS;
    int bactive = (tid < KS * 32);
    int bk = tid >> 5, bj = tid & 31;
    int ntm = n >> 7;
    int njobs = ntm * SK;
    int Kb = K / SK;
    for (int j = bstart; j < njobs; j += bstride) {
        int t = j % ntm, kh = j / ntm;
        int kbeg = kh * Kb, kend = kbeg + Kb;
        int bm = t << 7;
        float a0 = 0.f, a1 = 0.f, a2 = 0.f, a3 = 0.f;
        float ra[NA];
#pragma unroll
        for (int i = 0; i < NA; i++)
            ra[i] = a_elem(X, pos, skip, F1, F2, K, bm + am + i * (1024 / KS), kbeg + ak);
        float rb = bactive ? W[(size_t)(kbeg + bk) * 32 + bj] : 0.f;
        int cur = 0;
        __syncthreads();
        for (int kk = kbeg; kk < kend; kk += KS) {
            float* As = sh + cur * GB;
            float* Bs = As + ABUF;
#pragma unroll
            for (int i = 0; i < NA; i++)
                As[ak * 132 + am + i * (1024 / KS)] = ra[i];
            if (bactive) Bs[bk * 33 + bj] = rb;
            __syncthreads();
            if (kk + KS < kend) {
#pragma unroll
                for (int i = 0; i < NA; i++)
                    ra[i] = a_elem(X, pos, skip, F1, F2, K,
                                   bm + am + i * (1024 / KS), kk + KS + ak);
                rb = bactive ? W[(size_t)(kk + KS + bk) * 32 + bj] : 0.f;
            }
#pragma unroll
            for (int k = 0; k < KS; k++) {
                float4 aa = *(const float4*)&As[k * 132 + tm];
                float b  = Bs[k * 33 + tn];
                a0 += aa.x * b; a1 += aa.y * b;
                a2 += aa.z * b; a3 += aa.w * b;
            }
            cur ^= 1;
        }
        int gi = bm + tm;
        atomicAdd(&out[(size_t)gi * 32 + tn], a0);
        atomicAdd(&out[(size_t)(gi + 1) * 32 + tn], a1);
        atomicAdd(&out[(size_t)(gi + 2) * 32 + tn], a2);
        atomicAdd(&out[(size_t)(gi + 3) * 32 + tn], a3);
    }
}

// 64x64-tile GEMM, 1024 threads, 2x2 micro; double-buffered smem.
constexpr int GBUF64 = 16 * 66 + 16 * 66;
__device__ void gemm64_dev(const float* __restrict__ X,
                           const float* __restrict__ W, float* __restrict__ out,
                           int n, int K, int M, float* sh, int bstart, int bstride,
                           int SK) {
    int tid = threadIdx.x;
    int tm = (tid >> 5) << 1;
    int tn = (tid & 31) << 1;
    int lm = tid >> 4, lk = tid & 15;
    int bk = tid >> 6, bj = tid & 63;
    int ntn = (M + 63) >> 6;
    int ntm = n >> 6;
    int ntile = ntm * ntn;
    int njobs = ntile * SK;
    int Kb = K / SK;
    for (int j = bstart; j < njobs; j += bstride) {
        int t = j % ntile, kh = j / ntile;
        int kbeg = kh * Kb, kend = kbeg + Kb;
        int bm = (t / ntn) << 6, bn = (t % ntn) << 6;
        float a00 = 0.f, a01 = 0.f, a10 = 0.f, a11 = 0.f;
        float ra = X[(size_t)(bm + lm) * K + (kbeg + lk)];
        float rb = (bn + bj < M) ? W[(size_t)(kbeg + bk) * M + (bn + bj)] : 0.f;
        int cur = 0;
        __syncthreads();
        for (int kk = kbeg; kk < kend; kk += 16) {
            float* As = sh + cur * GBUF64;
            float* Bs = As + 16 * 66;
            As[lk * 66 + lm] = ra;
            Bs[bk * 66 + bj] = rb;
            __syncthreads();
            if (kk + 16 < kend) {
                ra = X[(size_t)(bm + lm) * K + (kk + 16 + lk)];
                rb = (bn + bj < M) ? W[(size_t)(kk + 16 + bk) * M + (bn + bj)] : 0.f;
            }
#pragma unroll
            for (int k = 0; k < 16; k++) {
                float2 aa = *(const float2*)&As[k * 66 + tm];
                float2 bb = *(const float2*)&Bs[k * 66 + tn];
                a00 += aa.x * bb.x; a01 += aa.x * bb.y;
                a10 += aa.y * bb.x; a11 += aa.y * bb.y;
            }
            cur ^= 1;
        }
        int gi = bm + tm, gj = bn + tn;
        if (gj < M) {
            atomicAdd(&out[(size_t)gi * M + gj], a00);
            atomicAdd(&out[(size_t)(gi + 1) * M + gj], a10);
            if (gj + 1 < M) {
                atomicAdd(&out[(size_t)gi * M + gj + 1], a01);
                atomicAdd(&out[(size_t)(gi + 1) * M + gj + 1], a11);
            }
        }
    }
}

// rank: 2048-row i-tiles, 2 rows per thread; CH-wide j-chunks in smem,
// vectorized ulonglong2 loads (CH even).
__device__ void rank_dev(const u64* __restrict__ key, int n, int CH,
                         int* __restrict__ rank, u64* shk) {
    int nti = n >> 11;
    int ntj = n / CH;
    for (int t = blockIdx.x; t < nti * ntj; t += gridDim.x) {
        int ti = t / ntj, tj = t - ti * ntj;
        int i0 = (ti << 11) + threadIdx.x;
        int j0 = tj * CH;
        __syncthreads();
        for (int l = threadIdx.x; l < CH; l += 1024) shk[l] = key[j0 + l];
        __syncthreads();
        u64 ka = key[i0], kb = key[i0 + 1024];
        int ca = 0, cb = 0;
        const ulonglong2* shk2 = (const ulonglong2*)shk;
#pragma unroll 4
        for (int j = 0; j < CH / 2; j++) {
            ulonglong2 kk = shk2[j];
            ca += (kk.x > ka) ? 1 : 0;
            ca += (kk.y > ka) ? 1 : 0;
            cb += (kk.x > kb) ? 1 : 0;
            cb += (kk.y > kb) ? 1 : 0;
        }
        if (ca) atomicAdd(&rank[i0], ca);
        if (cb) atomicAdd(&rank[i0 + 1024], cb);
    }
}

// gather with compile-time F (divisions become shifts)
template<int F>
__device__ void gather_dev(const float* __restrict__ x, const float* __restrict__ s,
                           const int* __restrict__ rank, int n, int k,
                           float* __restrict__ out, int* __restrict__ pos) {
    int gt = blockIdx.x * blockDim.x + threadIdx.x, NT = gridDim.x * blockDim.x;
    for (int t = gt; t < n * F; t += NT) {
        int i = t / F, f = t - i * F;
        int r = rank[i];
        if (f == 0) pos[i] = (r < k) ? r : -1;
        if (r < k) {
            float gate = 1.f / (1.f + expf(-s[i]));
            out[(size_t)r * F + f] = eluf(x[t] * gate);
        }
    }
}

__device__ void bmfilter_dev(const u32* __restrict__ bms, const u32* __restrict__ ssum,
                             int nws, int nssw, int nsrc, const int* __restrict__ rank,
                             int k, int nwd, u32* __restrict__ bmd) {
    int lane = threadIdx.x & 31;
    int wg = (blockIdx.x * blockDim.x + threadIdx.x) >> 5;
    int NWp = (gridDim.x * blockDim.x) >> 5;
    for (int i = wg; i < nsrc; i += NWp) {
        int b = rank[i];
        if (b >= k) continue;
        const u32* row = bms + (size_t)i * nws;
        const u32* srow = ssum + (size_t)i * nssw;
        for (int w = lane; w < nws; w += 32) {
            if (!((srow[w >> 5] >> (w & 31)) & 1u)) continue;
            u32 word = row[w];
            while (word) {
                int bit = __ffs(word) - 1; word &= word - 1;
                int ps = rank[(w << 5) + bit];
                if (ps < k) atomicOr(&bmd[(size_t)b * nwd + (ps >> 5)], 1u << (ps & 31));
            }
        }
    }
}

__device__ void dinvsum_dev(const u32* __restrict__ bm, int n, int nw, int nsw,
                            float* __restrict__ dv, u32* __restrict__ sum) {
    int lane = threadIdx.x & 31;
    int wg = (blockIdx.x * blockDim.x + threadIdx.x) >> 5;
    int NWp = (gridDim.x * blockDim.x) >> 5;
    for (int r = wg; r < n; r += NWp) {
        int c = 0;
        for (int g = 0; g < nsw; g++) {
            u32 word = bm[(size_t)r * nw + (g << 5) + lane];
            u32 m = __ballot_sync(0xffffffffu, word != 0u);
            c += __popc(word);
            if (lane == 0) sum[(size_t)r * nsw + g] = m;
        }
#pragma unroll
        for (int o = 16; o > 0; o >>= 1) c += __shfl_xor_sync(0xffffffffu, c, o);
        if (lane == 0) dv[r] = rsqrtf((float)(c + 1));
    }
}

// bitmap SpMM; NSEG column segments per row; neighbors batch-decoded (NB).
template<int FW, int NSEG>
__device__ void spmm_dev(const u32* __restrict__ bm, const u32* __restrict__ sum,
                         int nw, int nsw, const float* __restrict__ z,
                         const float* __restrict__ dv, const float* __restrict__ bias,
                         float* __restrict__ out, int n,
                         const float* __restrict__ p, float* __restrict__ ss,
                         u64* __restrict__ key) {
    const int F = FW * 32 * NSEG;
    const int NB = (FW <= 4) ? 4 : 2;
    int lane = threadIdx.x & 31;
    int wg = (blockIdx.x * blockDim.x + threadIdx.x) >> 5;
    int NWp = (gridDim.x * blockDim.x) >> 5;
    float invn = 0.f;
    float pl[FW];
    if (p && NSEG == 1) {
        float q = 0.f;
#pragma unroll
        for (int c = 0; c < FW; c++) { pl[c] = p[lane + 32 * c]; q += pl[c] * pl[c]; }
#pragma unroll
        for (int o = 16; o > 0; o >>= 1) q += __shfl_xor_sync(0xffffffffu, q, o);
        invn = rsqrtf(q);
    }
    for (int t = wg; t < n * NSEG; t += NWp) {
        int r  = (NSEG == 1) ? t : (t / NSEG);
        int co = (NSEG == 1) ? 0 : ((t - r * NSEG) * FW * 32);
        float dr = dv[r];
        float acc[FW];
#pragma unroll
        for (int c = 0; c < FW; c++)
            acc[c] = dr * z[(size_t)r * F + co + lane + 32 * c];
        const u32* row = bm + (size_t)r * nw;
        const u32* srow = sum + (size_t)r * nsw;
        int nbuf[NB];
        int m = 0;
        auto flush = [&](int mc) {
            float dvs[NB];
            float tmp[NB][FW];
#pragma unroll
            for (int i = 0; i < NB; i++) if (i < mc) dvs[i] = dv[nbuf[i]];
#pragma unroll
            for (int i = 0; i < NB; i++) if (i < mc) {
                const float* zs = z + (size_t)nbuf[i] * F + co + lane;
#pragma unroll
                for (int c = 0; c < FW; c++) tmp[i][c] = zs[32 * c];
            }
#pragma unroll
            for (int i = 0; i < NB; i++) if (i < mc)
#pragma unroll
                for (int c = 0; c < FW; c++) acc[c] += dvs[i] * tmp[i][c];
        };
        for (int sw = 0; sw < nsw; sw++) {
            u32 sword = srow[sw];
            while (sword) {
                int wb = __ffs(sword) - 1; sword &= sword - 1;
                int w = (sw << 5) + wb;
                u32 word = row[w];
                while (word) {
                    int b = __ffs(word) - 1; word &= word - 1;
                    nbuf[m++] = (w << 5) + b;
                    if (m == NB) { flush(NB); m = 0; }
                }
            }
        }
        if (m) flush(m);
        float sc = 0.f;
#pragma unroll
        for (int c = 0; c < FW; c++) {
            float v = eluf(dr * acc[c] + bias[co + lane + 32 * c]);
            out[(size_t)r * F + co + lane + 32 * c] = v;
            if (p && NSEG == 1) sc += v * pl[c];
        }
        if (p && NSEG == 1) {
#pragma unroll
            for (int o = 16; o > 0; o >>= 1) sc += __shfl_xor_sync(0xffffffffu, sc, o);
            if (lane == 0) {
                float sv = sc * invn;
                ss[r] = sv;
                key[r] = ((u64)ford(sv) << 32) | (u32)(~r);
            }
        }
    }
}

__device__ void csragg_dev(const float* __restrict__ z, const int* __restrict__ rp,
                           const int* __restrict__ col, const float* __restrict__ dv,
                           const float* __restrict__ bias, float* __restrict__ out,
                           const float* __restrict__ p, float* __restrict__ ss,
                           u64* __restrict__ key,
                           const int* __restrict__ batch, float* __restrict__ gsum,
                           u32* __restrict__ gmax, float* __restrict__ cnt) {
    int lane = threadIdx.x & 31;
    int wg = (blockIdx.x * blockDim.x + threadIdx.x) >> 5;
    int NWp = (gridDim.x * blockDim.x) >> 5;
    float invn = 0.f, pv = 0.f;
    if (p) {
        pv = p[lane];
        float q = pv * pv;
#pragma unroll
        for (int o = 16; o > 0; o >>= 1) q += __shfl_xor_sync(0xffffffffu, q, o);
        invn = rsqrtf(q);
    }
    float bl = bias[lane];
    for (int r = wg; r < NN; r += NWp) {
        float dr = dv[r];
        float acc = dr * z[r * 32 + lane];
        int e = rp[r], e1 = rp[r + 1];
        for (; e + 7 < e1; e += 8) {
            int s[8]; float d[8], v[8];
#pragma unroll
            for (int i = 0; i < 8; i++) s[i] = col[e + i];
#pragma unroll
            for (int i = 0; i < 8; i++) { d[i] = dv[s[i]]; v[i] = z[s[i] * 32 + lane]; }
#pragma unroll
            for (int i = 0; i < 8; i++) acc += d[i] * v[i];
        }
        for (; e < e1; e++) { int s = col[e]; acc += dv[s] * z[s * 32 + lane]; }
        float val = eluf(dr * acc + bl);
        if (out) {
            out[r * 32 + lane] = val;
            if (p) {
                float sc = val * pv;
#pragma unroll
                for (int o = 16; o > 0; o >>= 1) sc += __shfl_xor_sync(0xffffffffu, sc, o);
                if (lane == 0) {
                    float sv = sc * invn;
                    ss[r] = sv;
                    key[r] = ((u64)ford(sv) << 32) | (u32)(~r);
                }
            }
        } else {
            int g = batch[r];
            atomicAdd(&gsum[g * 32 + lane], val);
            atomicMax(&gmax[g * 32 + lane], ford(val));
            if (lane == 0) atomicAdd(&cnt[g], 1.f);
        }
    }
}

// --------------------------------- megakernel --------------------------------
__global__ void __launch_bounds__(1024, 1)
uk(const float* __restrict__ x, const int* __restrict__ ei, const int* __restrict__ batch,
   const float* W1, const float* b1, const float* W2, const float* b2,
   const float* W3, const float* b3, const float* W4, const float* b4,
   const float* W5, const float* b5, const float* W6, const float* b6,
   const float* W7, const float* b7, const float* p1, const float* p2, const float* p3,
   const float* Wl1, const float* Wc, const float* bc, float* __restrict__ out) {
    __shared__ __align__(16) float sh[12800];
    float* B = g_ws;
    float* ZA  = B + O_ZA;
    float* ZB  = B + O_ZB;
    int*  COL  = (int*)(B + O_COL);
    int*  DEG0 = (int*)(B + O_DEG0);
    float* DV0 = B + O_DINV0;
    float* DV2 = B + O_DINV2;
    float* DV4 = B + O_DINV4;
    float* DV6 = B + O_DINV6;
    float* SS  = B + O_S;
    u64*  KEY  = (u64*)(B + O_KEY);
    int*  RANK = (int*)(B + O_RANK);
    int*  POS0 = (int*)(B + O_POS0);
    int*  POS4 = (int*)(B + O_POS4);
    int*  POS6 = (int*)(B + O_POS6);
    int*  RP   = (int*)(B + O_RP);
    int*  OFF  = (int*)(B + O_OFF);
    u32*  BM2  = (u32*)(B + O_BM2);
    u32*  BM4  = (u32*)(B + O_BM4);
    u32*  BM6  = (u32*)(B + O_BM6);
    u32*  SUM2 = (u32*)(B + O_SUM2);
    u32*  SUM4 = (u32*)(B + O_SUM4);
    u32*  SUM6 = (u32*)(B + O_SUM6);
    float* GSUM= B + O_GSUM;
    u32*  GMAX = (u32*)(B + O_GMAX);
    float* CNT = B + O_CNT;

    int tid = threadIdx.x;
    int gt  = blockIdx.x * 1024 + tid;
    int NT  = gridDim.x * 1024;

    // B1: degree histogram (exactly <=2 edges/thread, loads batched) ; zeroing
    {
        int e0 = gt, e1 = gt + NT;
        int d0 = (e0 < EE) ? ei[EE + e0] : -1;
        int d1 = (e1 < EE) ? ei[EE + e1] : -1;
        if (d0 >= 0) atomicAdd(&DEG0[d0], 1);
        if (d1 >= 0) atomicAdd(&DEG0[d1], 1);
    }
    for (int i = gt; i < KK1 * NWB2; i += NT) BM2[i] = 0;
    for (int i = gt; i < NG * 32; i += NT) { GSUM[i] = 0.f; GMAX[i] = 0u; }
    for (int i = gt; i < NG; i += NT) CNT[i] = 0.f;
    zerof(ZA, NN * 32);
    zerof(ZB, KK1 * 64);
    gsync();

    // B2: block 0 CSR scan || GEMM1 splitK2 (ZA, M=32 path, KS=32)
    if (blockIdx.x == 0) {
        int base = tid * 8;
        int s = 0;
#pragma unroll
        for (int j = 0; j < 8; j++) s += DEG0[base + j];
        int* shi = (int*)sh;
        shi[tid] = s;
        __syncthreads();
        for (int o = 1; o < 1024; o <<= 1) {
            int v = (tid >= o) ? shi[tid - o] : 0;
            __syncthreads();
            shi[tid] += v;
            __syncthreads();
        }
        int run = shi[tid] - s;
#pragma unroll
        for (int j = 0; j < 8; j++) {
            int d = DEG0[base + j];
            RP[base + j] = run;
            OFF[base + j] = run;
            DV0[base + j] = rsqrtf((float)(d + 1));
            run += d;
        }
        if (tid == 1023) RP[NN] = run;
    } else {
        gemm32_dev<32>(x, nullptr, nullptr, 0, 0, W1, ZA, NN, 128, sh,
                       blockIdx.x - 1, gridDim.x - 1, 2);
    }
    gsync();

    // B3: CSR scatter (batched loads) ; re-zero DEG0
    {
        int e0 = gt, e1 = gt + NT;
        int s0 = 0, d0 = -1, s1 = 0, d1 = -1;
        if (e0 < EE) { s0 = ei[e0]; d0 = ei[EE + e0]; }
        if (e1 < EE) { s1 = ei[e1]; d1 = ei[EE + e1]; }
        if (d0 >= 0) { int pp = atomicAdd(&OFF[d0], 1); COL[pp] = s0; }
        if (d1 >= 0) { int pp = atomicAdd(&OFF[d1], 1); COL[pp] = s1; }
    }
    for (int i = gt; i < NN; i += NT) DEG0[i] = 0;
    gsync();

    // B4: X1 = csragg(ZA) + score1/key ; zero RANK
    csragg_dev(ZA, RP, COL, DV0, b1, B + O_X1, p1, SS, KEY,
               nullptr, nullptr, nullptr, nullptr);
    for (int i = gt; i < NN; i += NT) RANK[i] = 0;
    gsync();

    // B5: rank pool1 (128 tiles)
    rank_dev(KEY, NN, 256, RANK, (u64*)sh);
    gsync();

    // B6: gather1 -> X2 ; bm_edges (batched loads) -> BM2 ; zero BM4
    gather_dev<32>(B + O_X1, SS, RANK, NN, KK1, B + O_X2, POS0);
    {
        int e0 = gt, e1 = gt + NT;
        int a0 = 0, c0 = 0, a1 = 0, c1 = 0;
        bool h0 = e0 < EE, h1 = e1 < EE;
        if (h0) { a0 = ei[e0]; c0 = ei[EE + e0]; }
        if (h1) { a1 = ei[e1]; c1 = ei[EE + e1]; }
        int rs0 = KK1, rd0 = KK1, rs1 = KK1, rd1 = KK1;
        if (h0) { rs0 = RANK[a0]; rd0 = RANK[c0]; }
        if (h1) { rs1 = RANK[a1]; rd1 = RANK[c1]; }
        if (rs0 < KK1 && rd0 < KK1)
            atomicOr(&BM2[(size_t)rd0 * NWB2 + (rs0 >> 5)], 1u << (rs0 & 31));
        if (rs1 < KK1 && rd1 < KK1)
            atomicOr(&BM2[(size_t)rd1 * NWB2 + (rs1 >> 5)], 1u << (rs1 & 31));
    }
    for (int i = gt; i < KK2 * NWB4; i += NT) BM4[i] = 0;
    gsync();

    // B7: GEMM2 splitK2 (ZB, 64x64: 128 jobs) || dinvsum2
    gemm64_dev(B + O_X2, W2, ZB, KK1, 32, 64, sh, blockIdx.x, gridDim.x, 2);
    dinvsum_dev(BM2, KK1, NWB2, NSW2, DV2, SUM2);
    gsync();

    // B8: spmm2(ZB) -> X3 + score2 ; zero RANK ; zero ZA (GEMM3)
    spmm_dev<2, 1>(BM2, SUM2, NWB2, NSW2, ZB, DV2, b2, B + O_X3, KK1, p2, SS, KEY);
    for (int i = gt; i < KK1; i += NT) RANK[i] = 0;
    zerof(ZA, KK2 * 128);
    gsync();

    // B9: rank pool2 (128 tiles)
    rank_dev(KEY, KK1, 64, RANK, (u64*)sh);
    gsync();

    // B10: gather2 -> X4 ; bmfilter BM2->BM4 ; zero BM6
    gather_dev<64>(B + O_X3, SS, RANK, KK1, KK2, B + O_X4, POS4);
    bmfilter_dev(BM2, SUM2, NWB2, NSW2, KK1, RANK, KK2, NWB4, BM4);
    for (int i = gt; i < KK3 * NWB6; i += NT) BM6[i] = 0;
    gsync();

    // B11: GEMM3 splitK4 (ZA, KS=16) || dinvsum4
    gemm_dev<16>(B + O_X4, nullptr, nullptr, 0, 0, W3, ZA, KK2, 64, 128, sh,
                 blockIdx.x, gridDim.x, 4);
    dinvsum_dev(BM4, KK2, NWB4, NSW4, DV4, SUM4);
    gsync();

    // B12: spmm3(ZA) -> X5 + score3 ; zero RANK ; zero ZB (GEMM4)
    spmm_dev<4, 1>(BM4, SUM4, NWB4, NSW4, ZA, DV4, b3, B + O_X5, KK2, p3, SS, KEY);
    for (int i = gt; i < KK2; i += NT) RANK[i] = 0;
    zerof(ZB, KK3 * 256);
    gsync();

    // B13: rank pool3 (128 tiles, CH=16)
    rank_dev(KEY, KK2, 16, RANK, (u64*)sh);
    gsync();

    // B14: gather3 -> X6 ; bmfilter BM4->BM6
    gather_dev<128>(B + O_X5, SS, RANK, KK2, KK3, B + O_X6, POS6);
    bmfilter_dev(BM4, SUM4, NWB4, NSW4, KK2, RANK, KK3, NWB6, BM6);
    gsync();

    // B15: GEMM4 splitK4 (ZB, KS=32: 1 slab) || dinvsum6
    gemm_dev<32>(B + O_X6, nullptr, nullptr, 0, 0, W4, ZB, KK3, 128, 256, sh,
                 blockIdx.x, gridDim.x, 4);
    dinvsum_dev(BM6, KK3, NWB6, NSW6, DV6, SUM6);
    gsync();

    // B16: spmm4(ZB) -> X7 (4 col-segments) ; zero ZA (GEMM5)
    spmm_dev<2, 4>(BM6, SUM6, NWB6, NSW6, ZB, DV6, b4, B + O_X7, KK3,
                   nullptr, nullptr, nullptr);
    zerof(ZA, KK2 * 128);
    gsync();

    // B17: GEMM5 splitK4 (ZA, KS=32: 3 slabs) fused concat(X7/POS6, X5)
    gemm_dev<32>(B + O_X7, POS6, B + O_X5, 256, 128, W5, ZA, KK2, 384, 128, sh,
                 blockIdx.x, gridDim.x, 4);
    gsync();

    // B18: spmm5(ZA) -> X9 (2 col-segments) ; zero ZB (GEMM6)
    spmm_dev<2, 2>(BM4, SUM4, NWB4, NSW4, ZA, DV4, b5, B + O_X9, KK2,
                   nullptr, nullptr, nullptr);
    zerof(ZB, KK1 * 64);
    gsync();

    // B19: GEMM6 splitK4 (ZB, KS=16: 3 slabs) fused concat(X9/POS4, X3)
    gemm_dev<16>(B + O_X9, POS4, B + O_X3, 128, 64, W6, ZB, KK1, 192, 64, sh,
                 blockIdx.x, gridDim.x, 4);
    gsync();

    // B20: spmm6(ZB) -> X11 ; zero ZA (GEMM7)
    spmm_dev<2, 1>(BM2, SUM2, NWB2, NSW2, ZB, DV2, b6, B + O_X11, KK1,
                   nullptr, nullptr, nullptr);
    zerof(ZA, NN * 32);
    gsync();

    // B21: GEMM7 splitK2 (ZA, M=32 path, KS=16) fused concat(X11/POS0, X1)
    gemm32_dev<16>(B + O_X11, POS0, B + O_X1, 64, 32, W7, ZA, NN, 96, sh,
                   blockIdx.x, gridDim.x, 2);
    gsync();

    // B22: final csragg(ZA) with fused readout
    csragg_dev(ZA, RP, COL, DV0, b7, nullptr, nullptr, nullptr, nullptr,
               batch, GSUM, GMAX, CNT);
    gsync();

    // ---- head ----
    if (blockIdx.x < NG) {
        int g = blockIdx.x;
        float* h  = sh;
        float* h2 = sh + 64;
        float* lg = sh + 128;
        if (tid < 64)
            h[tid] = eluf(tid < 32 ? unford(GMAX[g * 32 + tid])
                                   : GSUM[g * 32 + (tid - 32)] / CNT[g]);
        __syncthreads();
        if (tid < 64) {
            float acc = 0.f;
#pragma unroll
            for (int k = 0; k < 64; k++) acc += h[k] * Wl1[k * 64 + tid];
            h2[tid] = eluf(acc);
        }
        __syncthreads();
        if (tid < 10) {
            float a = bc[tid];
#pragma unroll
            for (int k = 0; k < 64; k++) a += h2[k] * Wc[k * 10 + tid];
            lg[tid] = a;
        }
        __syncthreads();
        if (tid == 0) {
            float m = lg[0];
            for (int c = 1; c < 10; c++) m = fmaxf(m, lg[c]);
            float se = 0.f;
            for (int c = 0; c < 10; c++) se += expf(lg[c] - m);
            sh[140] = m + logf(se);
        }
        __syncthreads();
        if (tid < 10) out[g * 10 + tid] = lg[tid] - sh[140];
    }
}

// ------------------------------- launcher ------------------------------------
extern "C" void kernel_launch(void* const* d_in, const int* in_sizes, int n_in,
                              void* d_out, int out_size) {
    (void)in_sizes; (void)n_in; (void)out_size;
    const float* x    = (const float*)d_in[0];
    const int*   ei   = (const int*)d_in[1];
    const int*   batch= (const int*)d_in[2];
    const float* W1 = (const float*)d_in[3],  *b1 = (const float*)d_in[4];
    const float* W2 = (const float*)d_in[5],  *b2 = (const float*)d_in[6];
    const float* W3 = (const float*)d_in[7],  *b3 = (const float*)d_in[8];
    const float* W4 = (const float*)d_in[9],  *b4 = (const float*)d_in[10];
    const float* W5 = (const float*)d_in[11], *b5 = (const float*)d_in[12];
    const float* W6 = (const float*)d_in[13], *b6 = (const float*)d_in[14];
    const float* W7 = (const float*)d_in[15], *b7 = (const float*)d_in[16];
    const float* p1 = (const float*)d_in[17];
    const float* p2 = (const float*)d_in[18];
    const float* p3 = (const float*)d_in[19];
    const float* Wl1= (const float*)d_in[20];
    const float* Wc = (const float*)d_in[21];
    const float* bc = (const float*)d_in[22];
    float* out = (float*)d_out;

    int dev = 0;
    cudaGetDevice(&dev);
    int nsm = 148;
    cudaDeviceGetAttribute(&nsm, cudaDevAttrMultiProcessorCount, dev);

    uk<<<nsm, 1024>>>(x, ei, batch, W1, b1, W2, b2, W3, b3, W4, b4,
                      W5, b5, W6, b6, W7, b7, p1, p2, p3, Wl1, Wc, bc, out);
}